// round 2
// baseline (speedup 1.0000x reference)
#include <cuda_runtime.h>
#include <cstdint>
#include <cstdio>

#define B_    64
#define T_    256
#define E_    256
#define H_    512
#define H4_   2048
#define TAGS_ 50

// ---------------- scratch (device globals; no allocations allowed) ----------
__device__ float g_e[B_ * T_ * E_];                       // [B*T, E]   16.7 MB
__device__ float g_preF[(size_t)B_ * T_ * H4_];           // [B*T, 4H]  128 MB
__device__ float g_preB[(size_t)B_ * T_ * H4_];           // [B*T, 4H]  128 MB
__device__ float g_out1[(size_t)B_ * T_ * 2 * H_];        // [B*T, 2H]  64 MB
__device__ float g_out2[(size_t)B_ * T_ * 2 * H_];        // [B*T, 2H]  64 MB
__device__ float g_hF[2][B_ * H_];                        // ping-pong h (fwd)
__device__ float g_hB[2][B_ * H_];                        // ping-pong h (bwd)
__device__ unsigned g_bar;                                 // grid barrier counter
__device__ int g_is64;                                     // 1 if x/lengths are int64
__device__ int g_len[B_];                                  // lengths as int32

// ---------------- helpers ---------------------------------------------------
__device__ __forceinline__ float sigmoidf_(float x) {
    return 1.0f / (1.0f + __expf(-x));
}

// ---------------- dtype detect + lengths prep -------------------------------
// If inputs are int64 (little-endian), every odd 32-bit word of x is 0
// (token ids < 50000). For genuine int32 data the odds of 16 consecutive odd
// words being zero is ~(1/50000)^16.
__global__ void detect_kernel(const void* x, const void* lengths) {
    __shared__ int s64;
    if (threadIdx.x == 0) {
        const int* xi = (const int*)x;
        int flag = 1;
        for (int i = 1; i <= 16; ++i)
            if (xi[2 * i + 1] != 0) flag = 0;
        g_is64 = flag;
        s64 = flag;
    }
    __syncthreads();
    if (threadIdx.x < B_) {
        int l = s64 ? (int)((const long long*)lengths)[threadIdx.x]
                    : ((const int*)lengths)[threadIdx.x];
        g_len[threadIdx.x] = l;
    }
}

// ---------------- embedding gather ------------------------------------------
__global__ void gather_kernel(const void* x, const float* __restrict__ emb) {
    const int row = blockIdx.x;           // 0..B*T-1
    long long idx = g_is64 ? ((const long long*)x)[row]
                           : (long long)((const int*)x)[row];
    const float4* src = (const float4*)(emb + (size_t)idx * E_);
    float4* dst = (float4*)(g_e + (size_t)row * E_);
    dst[threadIdx.x] = src[threadIdx.x];  // 64 threads * float4 = 256 floats
}

// ---------------- init (zero h ping-pong buffers + barrier) -----------------
__global__ void init_state_kernel() {
    int i = blockIdx.x * blockDim.x + threadIdx.x;
    const int n = 2 * B_ * H_;
    if (i < n) {
        ((float*)g_hF)[i] = 0.0f;
        ((float*)g_hB)[i] = 0.0f;
    }
    if (i == 0) g_bar = 0u;
}

// ---------------- fp32 SGEMM: C[M,N] = A[M,K] @ W[N,K]^T + bias[N] ----------
// 128x128 tile, BK=8, 256 threads, 8x8 per-thread microtile.
__global__ void __launch_bounds__(256, 1)
sgemm_nt_bias(const float* __restrict__ A, const float* __restrict__ Bw,
              const float* __restrict__ bias, float* __restrict__ C,
              int M, int N, int K) {
    __shared__ __align__(16) float sA[8][128];
    __shared__ __align__(16) float sB[8][128];
    const int tid = threadIdx.x;
    const int bm = blockIdx.y * 128;
    const int bn = blockIdx.x * 128;
    const int lr = tid >> 1;              // 0..127 load row
    const int lc = (tid & 1) * 4;         // 0 or 4
    const int tr = (tid >> 4) * 8;        // compute row base
    const int tc = (tid & 15) * 8;        // compute col base

    float acc[8][8];
#pragma unroll
    for (int i = 0; i < 8; ++i)
#pragma unroll
        for (int j = 0; j < 8; ++j) acc[i][j] = 0.0f;

    const float* Ap = A + (size_t)(bm + lr) * K + lc;
    const float* Bp = Bw + (size_t)(bn + lr) * K + lc;

    for (int k0 = 0; k0 < K; k0 += 8) {
        const float4 av = *(const float4*)(Ap + k0);
        const float4 bv = *(const float4*)(Bp + k0);
        __syncthreads();
        sA[lc + 0][lr] = av.x; sA[lc + 1][lr] = av.y;
        sA[lc + 2][lr] = av.z; sA[lc + 3][lr] = av.w;
        sB[lc + 0][lr] = bv.x; sB[lc + 1][lr] = bv.y;
        sB[lc + 2][lr] = bv.z; sB[lc + 3][lr] = bv.w;
        __syncthreads();
#pragma unroll
        for (int kk = 0; kk < 8; ++kk) {
            const float4 a0 = *(const float4*)&sA[kk][tr];
            const float4 a1 = *(const float4*)&sA[kk][tr + 4];
            const float4 b0 = *(const float4*)&sB[kk][tc];
            const float4 b1 = *(const float4*)&sB[kk][tc + 4];
            const float ra[8] = {a0.x, a0.y, a0.z, a0.w, a1.x, a1.y, a1.z, a1.w};
            const float rb[8] = {b0.x, b0.y, b0.z, b0.w, b1.x, b1.y, b1.z, b1.w};
#pragma unroll
            for (int i = 0; i < 8; ++i)
#pragma unroll
                for (int j = 0; j < 8; ++j) acc[i][j] += ra[i] * rb[j];
        }
    }

    const float4 bb0 = *(const float4*)&bias[bn + tc];
    const float4 bb1 = *(const float4*)&bias[bn + tc + 4];
#pragma unroll
    for (int i = 0; i < 8; ++i) {
        float4 v0 = make_float4(acc[i][0] + bb0.x, acc[i][1] + bb0.y,
                                acc[i][2] + bb0.z, acc[i][3] + bb0.w);
        float4 v1 = make_float4(acc[i][4] + bb1.x, acc[i][5] + bb1.y,
                                acc[i][6] + bb1.z, acc[i][7] + bb1.w);
        float* cp = C + (size_t)(bm + tr + i) * N + bn + tc;
        *(float4*)cp = v0;
        *(float4*)(cp + 4) = v1;
    }
}

// ---------------- persistent BiLSTM layer (both directions) -----------------
// grid = 128 CTAs: bx>>6 = dir (0 fwd, 1 bwd), bx&63 = h-column group (8 cols).
// Each step: gates[64,32] = h[64,512] @ W[32cols,512]^T (cols = {q*512+cg*8+j}),
// then gated update; c/h state of owned columns lives in registers.
__global__ void __launch_bounds__(256, 1)
lstm_layer_kernel(const float* __restrict__ preF, const float* __restrict__ preB,
                  const float* __restrict__ whF, const float* __restrict__ whB,
                  float* __restrict__ outBuf) {
    __shared__ __align__(16) float sH[64][68];   // [k][row], padded
    __shared__ __align__(16) float sW[64][34];   // [k][col], padded
    __shared__ __align__(16) float sG[64][33];   // gates [row][col]
    __shared__ int sLen[B_];

    const int tid = threadIdx.x;
    const int bx  = blockIdx.x;
    const int dir = bx >> 6;
    const int cg  = bx & 63;

    const float* __restrict__ pre = dir ? preB : preF;
    const float* __restrict__ W   = dir ? whB : whF;
    float* hbase = dir ? &g_hB[0][0] : &g_hF[0][0];

    if (tid < B_) sLen[tid] = g_len[tid];
    __syncthreads();

    // GEMM microtile mapping: 4 rows x 2 cols per thread
    const int rg = (tid & 15) * 4;
    const int cp = (tid >> 4) * 2;
    // W tile loader mapping
    const int wc  = tid >> 3;               // 0..31 (linear gate col)
    const int wkq = (tid & 7) * 8;           // k offset within 64-chunk
    const int wgcol = (wc >> 3) * 512 + cg * 8 + (wc & 7);
    // h tile loader mapping
    const int hrow = tid & 63;
    const int hkq  = (tid >> 6) * 16;

    float hreg[2] = {0.0f, 0.0f};
    float creg[2] = {0.0f, 0.0f};

    for (int t = 0; t < T_; ++t) {
        const float* __restrict__ hprev = hbase + (size_t)(t & 1) * (B_ * H_);
        float acc[4][2];
#pragma unroll
        for (int i = 0; i < 4; ++i) { acc[i][0] = 0.0f; acc[i][1] = 0.0f; }

#pragma unroll 1
        for (int kt = 0; kt < 8; ++kt) {
            const int k0 = kt * 64;
            // global -> regs (bypass L1: h is produced by other CTAs)
            const float* hp = hprev + (size_t)hrow * H_ + k0 + hkq;
            float4 hv0 = __ldcg((const float4*)(hp + 0));
            float4 hv1 = __ldcg((const float4*)(hp + 4));
            float4 hv2 = __ldcg((const float4*)(hp + 8));
            float4 hv3 = __ldcg((const float4*)(hp + 12));
            const float* wp = W + (size_t)wgcol * H_ + k0 + wkq;
            float4 wv0 = *(const float4*)(wp + 0);
            float4 wv1 = *(const float4*)(wp + 4);
            __syncthreads();   // previous tile fully consumed
            sH[hkq + 0][hrow] = hv0.x; sH[hkq + 1][hrow] = hv0.y;
            sH[hkq + 2][hrow] = hv0.z; sH[hkq + 3][hrow] = hv0.w;
            sH[hkq + 4][hrow] = hv1.x; sH[hkq + 5][hrow] = hv1.y;
            sH[hkq + 6][hrow] = hv1.z; sH[hkq + 7][hrow] = hv1.w;
            sH[hkq + 8][hrow] = hv2.x; sH[hkq + 9][hrow] = hv2.y;
            sH[hkq +10][hrow] = hv2.z; sH[hkq +11][hrow] = hv2.w;
            sH[hkq +12][hrow] = hv3.x; sH[hkq +13][hrow] = hv3.y;
            sH[hkq +14][hrow] = hv3.z; sH[hkq +15][hrow] = hv3.w;
            sW[wkq + 0][wc] = wv0.x; sW[wkq + 1][wc] = wv0.y;
            sW[wkq + 2][wc] = wv0.z; sW[wkq + 3][wc] = wv0.w;
            sW[wkq + 4][wc] = wv1.x; sW[wkq + 5][wc] = wv1.y;
            sW[wkq + 6][wc] = wv1.z; sW[wkq + 7][wc] = wv1.w;
            __syncthreads();
#pragma unroll
            for (int k = 0; k < 64; ++k) {
                const float4 a = *(const float4*)&sH[k][rg];
                const float2 b = *(const float2*)&sW[k][cp];
                acc[0][0] += a.x * b.x; acc[0][1] += a.x * b.y;
                acc[1][0] += a.y * b.x; acc[1][1] += a.y * b.y;
                acc[2][0] += a.z * b.x; acc[2][1] += a.z * b.y;
                acc[3][0] += a.w * b.x; acc[3][1] += a.w * b.y;
            }
        }
        __syncthreads();
#pragma unroll
        for (int i = 0; i < 4; ++i) {
            sG[rg + i][cp]     = acc[i][0];
            sG[rg + i][cp + 1] = acc[i][1];
        }
        __syncthreads();

        float* hnext = hbase + (size_t)((t + 1) & 1) * (B_ * H_);
#pragma unroll
        for (int u = 0; u < 2; ++u) {
            const int e = tid + u * 256;
            const int row = e >> 3;
            const int hc  = e & 7;
            const int len = sLen[row];
            const bool valid = (t < len);
            int pos;
            if (dir) pos = valid ? (len - 1 - t) : t;   // bwd: reversed position
            else     pos = t;
            const size_t pb = ((size_t)row * T_ + pos) * H4_ + cg * 8 + hc;
            const float gi = sG[row][hc]      + pre[pb];
            const float gf = sG[row][8 + hc]  + pre[pb + 512];
            const float gg = sG[row][16 + hc] + pre[pb + 1024];
            const float go = sG[row][24 + hc] + pre[pb + 1536];
            const float iv = sigmoidf_(gi);
            const float fv = sigmoidf_(gf);
            const float gv = tanhf(gg);
            const float ov = sigmoidf_(go);
            const float cn = fv * creg[u] + iv * gv;
            const float hn = ov * tanhf(cn);
            if (valid) { creg[u] = cn; hreg[u] = hn; }
            outBuf[((size_t)row * T_ + pos) * (2 * H_) + dir * H_ + cg * 8 + hc] =
                valid ? hn : 0.0f;
            hnext[(size_t)row * H_ + cg * 8 + hc] = hreg[u];
        }

        // grid barrier (monotonic counter; 128 co-resident CTAs)
        __threadfence();
        __syncthreads();
        if (tid == 0) {
            atomicAdd(&g_bar, 1u);
            const unsigned tgt = (unsigned)(t + 1) * gridDim.x;
            while (*(volatile unsigned*)&g_bar < tgt) { __nanosleep(64); }
        }
        __syncthreads();
    }
}

// ---------------- classifier: logits = out2 @ cls_w^T + cls_b ---------------
__global__ void __launch_bounds__(256, 1)
classifier_kernel(const float* __restrict__ clsW, const float* __restrict__ clsB,
                  float* __restrict__ out) {
    __shared__ __align__(16) float sX[8][1028];
    const int tid = threadIdx.x;
    const size_t r0 = (size_t)blockIdx.x * 8;
    const float* src = g_out2 + r0 * (2 * H_);
    for (int i = tid; i < 8 * 256; i += 256) {
        const int rr = i >> 8;
        const int kk = (i & 255) * 4;
        *(float4*)&sX[rr][kk] = *(const float4*)(src + (size_t)rr * 1024 + kk);
    }
    __syncthreads();
    for (int e = tid; e < 8 * TAGS_; e += 256) {
        const int r = e & 7;
        const int c = e >> 3;
        const float* w = clsW + (size_t)c * 1024;
        float s0 = 0.f, s1 = 0.f, s2 = 0.f, s3 = 0.f;
#pragma unroll 8
        for (int k = 0; k < 1024; k += 4) {
            const float4 a = *(const float4*)&sX[r][k];
            const float4 b = __ldg((const float4*)(w + k));
            s0 += a.x * b.x; s1 += a.y * b.y; s2 += a.z * b.z; s3 += a.w * b.w;
        }
        out[(r0 + r) * TAGS_ + c] = s0 + s1 + s2 + s3 + clsB[c];
    }
}

// ---------------- host launcher ---------------------------------------------
extern "C" void kernel_launch(void* const* d_in, const int* in_sizes, int n_in,
                              void* d_out, int out_size) {
    (void)in_sizes; (void)n_in; (void)out_size;
    const void*  x        = d_in[0];
    const void*  lengths  = d_in[1];
    const float* emb      = (const float*)d_in[2];
    const float* w_ih_f1  = (const float*)d_in[3];
    const float* w_hh_f1  = (const float*)d_in[4];
    const float* b_f1     = (const float*)d_in[5];
    const float* w_ih_b1  = (const float*)d_in[6];
    const float* w_hh_b1  = (const float*)d_in[7];
    const float* b_b1     = (const float*)d_in[8];
    const float* w_ih_f2  = (const float*)d_in[9];
    const float* w_hh_f2  = (const float*)d_in[10];
    const float* b_f2     = (const float*)d_in[11];
    const float* w_ih_b2  = (const float*)d_in[12];
    const float* w_hh_b2  = (const float*)d_in[13];
    const float* b_b2     = (const float*)d_in[14];
    const float* cls_w    = (const float*)d_in[15];
    const float* cls_b    = (const float*)d_in[16];
    float* out = (float*)d_out;

    float *pE, *pPF, *pPB, *pO1, *pO2;
    cudaGetSymbolAddress((void**)&pE,  g_e);
    cudaGetSymbolAddress((void**)&pPF, g_preF);
    cudaGetSymbolAddress((void**)&pPB, g_preB);
    cudaGetSymbolAddress((void**)&pO1, g_out1);
    cudaGetSymbolAddress((void**)&pO2, g_out2);

    const int M = B_ * T_;                       // 16384
    const dim3 gemm_grid(H4_ / 128, M / 128);    // (16, 128)

    detect_kernel<<<1, 64>>>(x, lengths);
    gather_kernel<<<M, 64>>>(x, emb);
    init_state_kernel<<<256, 256>>>();

    // layer 1 pre-activations (K = E = 256)
    sgemm_nt_bias<<<gemm_grid, 256>>>(pE, w_ih_f1, b_f1, pPF, M, H4_, E_);
    sgemm_nt_bias<<<gemm_grid, 256>>>(pE, w_ih_b1, b_b1, pPB, M, H4_, E_);
    lstm_layer_kernel<<<128, 256>>>(pPF, pPB, w_hh_f1, w_hh_b1, pO1);

    init_state_kernel<<<256, 256>>>();

    // layer 2 pre-activations (K = 2H = 1024)
    sgemm_nt_bias<<<gemm_grid, 256>>>(pO1, w_ih_f2, b_f2, pPF, M, H4_, 2 * H_);
    sgemm_nt_bias<<<gemm_grid, 256>>>(pO1, w_ih_b2, b_b2, pPB, M, H4_, 2 * H_);
    lstm_layer_kernel<<<128, 256>>>(pPF, pPB, w_hh_f2, w_hh_b2, pO2);

    classifier_kernel<<<M / 8, 256>>>(cls_w, cls_b, out);
}

// round 3
// speedup vs baseline: 1.2576x; 1.2576x over previous
#include <cuda_runtime.h>
#include <cstdint>
#include <cstdio>

#define B_    64
#define T_    256
#define E_    256
#define H_    512
#define H4_   2048
#define TAGS_ 50

#define SW_STRIDE 36                       // 512x36 floats (pad for bank spread)
#define SMEM_FLOATS (512 * SW_STRIDE + 512 * 64 + 64)
#define SMEM_BYTES  (SMEM_FLOATS * 4)

// ---------------- scratch (device globals; no allocations allowed) ----------
__device__ float g_e[B_ * T_ * E_];
__device__ float g_preF[(size_t)B_ * T_ * H4_];
__device__ float g_preB[(size_t)B_ * T_ * H4_];
__device__ float g_out1[(size_t)B_ * T_ * 2 * H_];
__device__ float g_out2[(size_t)B_ * T_ * 2 * H_];
__device__ float g_hF[2][H_ * B_];          // transposed: [k][row]
__device__ float g_hB[2][H_ * B_];
__device__ unsigned g_bar;
__device__ int g_is64;
__device__ int g_len[B_];

// ---------------- helpers ---------------------------------------------------
__device__ __forceinline__ float sigmoidf_(float x) {
    return 1.0f / (1.0f + __expf(-x));
}
__device__ __forceinline__ unsigned long long splat2(float v) {
    unsigned long long r;
    asm("mov.b64 %0, {%1, %1};" : "=l"(r) : "f"(v));
    return r;
}
__device__ __forceinline__ void fma2(unsigned long long& d,
                                     unsigned long long a, unsigned long long b) {
    asm("fma.rn.f32x2 %0, %1, %2, %0;" : "+l"(d) : "l"(a), "l"(b));
}
__device__ __forceinline__ float2 unpack2(unsigned long long v) {
    float2 u;
    asm("mov.b64 {%0, %1}, %2;" : "=f"(u.x), "=f"(u.y) : "l"(v));
    return u;
}

// ---------------- dtype detect + lengths prep -------------------------------
__global__ void detect_kernel(const void* x, const void* lengths) {
    __shared__ int s64;
    if (threadIdx.x == 0) {
        const int* xi = (const int*)x;
        int flag = 1;
        for (int i = 1; i <= 16; ++i)
            if (xi[2 * i + 1] != 0) flag = 0;
        g_is64 = flag;
        s64 = flag;
    }
    __syncthreads();
    if (threadIdx.x < B_) {
        int l = s64 ? (int)((const long long*)lengths)[threadIdx.x]
                    : ((const int*)lengths)[threadIdx.x];
        g_len[threadIdx.x] = l;
    }
}

// ---------------- embedding gather ------------------------------------------
__global__ void gather_kernel(const void* x, const float* __restrict__ emb) {
    const int row = blockIdx.x;
    long long idx = g_is64 ? ((const long long*)x)[row]
                           : (long long)((const int*)x)[row];
    const float4* src = (const float4*)(emb + (size_t)idx * E_);
    float4* dst = (float4*)(g_e + (size_t)row * E_);
    dst[threadIdx.x] = src[threadIdx.x];
}

// ---------------- init (zero h buffers + barrier) ----------------------------
__global__ void init_state_kernel() {
    int i = blockIdx.x * blockDim.x + threadIdx.x;
    const int n = 2 * B_ * H_;
    if (i < n) {
        ((float*)g_hF)[i] = 0.0f;
        ((float*)g_hB)[i] = 0.0f;
    }
    if (i == 0) g_bar = 0u;
}

// ---------------- fp32 SGEMM (f32x2): C = A @ W^T + bias --------------------
__global__ void __launch_bounds__(256, 1)
sgemm_nt_bias(const float* __restrict__ A, const float* __restrict__ Bw,
              const float* __restrict__ bias, float* __restrict__ C,
              int M, int N, int K) {
    __shared__ __align__(16) float sA[8][128];
    __shared__ __align__(16) float sB[8][128];
    const int tid = threadIdx.x;
    const int bm = blockIdx.y * 128;
    const int bn = blockIdx.x * 128;
    const int lr = tid >> 1;
    const int lc = (tid & 1) * 4;
    const int tr = (tid >> 4) * 8;
    const int tc = (tid & 15) * 8;

    unsigned long long acc2[8][4];
#pragma unroll
    for (int i = 0; i < 8; ++i)
#pragma unroll
        for (int j = 0; j < 4; ++j) acc2[i][j] = 0ull;

    const float* Ap = A + (size_t)(bm + lr) * K + lc;
    const float* Bp = Bw + (size_t)(bn + lr) * K + lc;

    for (int k0 = 0; k0 < K; k0 += 8) {
        const float4 av = *(const float4*)(Ap + k0);
        const float4 bv = *(const float4*)(Bp + k0);
        __syncthreads();
        sA[lc + 0][lr] = av.x; sA[lc + 1][lr] = av.y;
        sA[lc + 2][lr] = av.z; sA[lc + 3][lr] = av.w;
        sB[lc + 0][lr] = bv.x; sB[lc + 1][lr] = bv.y;
        sB[lc + 2][lr] = bv.z; sB[lc + 3][lr] = bv.w;
        __syncthreads();
#pragma unroll
        for (int kk = 0; kk < 8; ++kk) {
            const float4 a0 = *(const float4*)&sA[kk][tr];
            const float4 a1 = *(const float4*)&sA[kk][tr + 4];
            const ulonglong2 b0 = *(const ulonglong2*)&sB[kk][tc];
            const ulonglong2 b1 = *(const ulonglong2*)&sB[kk][tc + 4];
            const unsigned long long bp[4] = {b0.x, b0.y, b1.x, b1.y};
            const float ra[8] = {a0.x, a0.y, a0.z, a0.w, a1.x, a1.y, a1.z, a1.w};
#pragma unroll
            for (int i = 0; i < 8; ++i) {
                const unsigned long long as = splat2(ra[i]);
#pragma unroll
                for (int j = 0; j < 4; ++j) fma2(acc2[i][j], as, bp[j]);
            }
        }
    }

    const float4 bb0 = *(const float4*)&bias[bn + tc];
    const float4 bb1 = *(const float4*)&bias[bn + tc + 4];
#pragma unroll
    for (int i = 0; i < 8; ++i) {
        const float2 c0 = unpack2(acc2[i][0]);
        const float2 c1 = unpack2(acc2[i][1]);
        const float2 c2 = unpack2(acc2[i][2]);
        const float2 c3 = unpack2(acc2[i][3]);
        float4 v0 = make_float4(c0.x + bb0.x, c0.y + bb0.y, c1.x + bb0.z, c1.y + bb0.w);
        float4 v1 = make_float4(c2.x + bb1.x, c2.y + bb1.y, c3.x + bb1.z, c3.y + bb1.w);
        float* cp = C + (size_t)(bm + tr + i) * N + bn + tc;
        *(float4*)cp = v0;
        *(float4*)(cp + 4) = v1;
    }
}

// ---------------- persistent BiLSTM layer ------------------------------------
// grid = 128 CTAs x 128 threads. bx>>6 = dir, bx&63 = column group (8 h-cols,
// 32 gate-cols). W_hh slice persistent in smem. h stored transposed [k][row]
// in global, staged as a straight copy each step. GEMM: 4 warps split K
// (128 each), per-lane 8x8 microtile, f32x2 packed FMAs; warp partials
// reduced through the freed sH region; fused elementwise; 1 grid barrier/step.
__global__ void __launch_bounds__(128, 1)
lstm_layer_kernel(const float* __restrict__ preF, const float* __restrict__ preB,
                  const float* __restrict__ whF, const float* __restrict__ whB,
                  float* __restrict__ outBuf) {
    extern __shared__ __align__(16) float smem_[];
    float* sW = smem_;                          // [512][SW_STRIDE]
    float* sH = smem_ + 512 * SW_STRIDE;        // [512][64]; reused as sGp[4][32][64]
    int* sLen = (int*)(smem_ + 512 * SW_STRIDE + 512 * 64);

    const int tid  = threadIdx.x;
    const int bx   = blockIdx.x;
    const int dir  = bx >> 6;
    const int cg   = bx & 63;
    const int lane = tid & 31;
    const int wrp  = tid >> 5;

    const float* __restrict__ pre = dir ? preB : preF;
    const float* __restrict__ W   = dir ? whB : whF;
    float* hbase = dir ? &g_hB[0][0] : &g_hF[0][0];

    // one-time: W slice -> smem (coalesced in k), lengths
    if (tid < B_) sLen[tid] = g_len[tid];
    for (int idx = tid; idx < 32 * 512; idx += 128) {
        const int j = idx >> 9;                 // 0..31
        const int k = idx & 511;
        const int gcol = (j >> 3) * 512 + cg * 8 + (j & 7);
        sW[k * SW_STRIDE + j] = W[(size_t)gcol * H_ + k];
    }
    __syncthreads();

    // GEMM microtile mapping
    const int rg = (lane >> 2) * 8;             // row base (8 rows)
    const int cb = (lane & 3) * 8;              // col base (8 cols)
    const int k0 = wrp * 128;

    float creg[4] = {0.f, 0.f, 0.f, 0.f};
    float hreg[4] = {0.f, 0.f, 0.f, 0.f};

    for (int t = 0; t < T_; ++t) {
        // ---- stage h (straight copy, [k][row] both sides) ----
        {
            const float4* src = (const float4*)(hbase + (size_t)(t & 1) * (H_ * B_));
            float4* dst = (float4*)sH;
#pragma unroll 8
            for (int i = tid; i < 8192; i += 128)
                dst[i] = __ldcg(src + i);
        }
        __syncthreads();

        // ---- GEMM: this warp's K slice over the full 64x32 tile ----
        unsigned long long acc[4][8];
#pragma unroll
        for (int rp = 0; rp < 4; ++rp)
#pragma unroll
            for (int c = 0; c < 8; ++c) acc[rp][c] = 0ull;

#pragma unroll 2
        for (int k = k0; k < k0 + 128; ++k) {
            const ulonglong2 h01 = *(const ulonglong2*)&sH[k * 64 + rg];
            const ulonglong2 h23 = *(const ulonglong2*)&sH[k * 64 + rg + 4];
            const float4 w0 = *(const float4*)&sW[k * SW_STRIDE + cb];
            const float4 w1 = *(const float4*)&sW[k * SW_STRIDE + cb + 4];
            const unsigned long long hp[4] = {h01.x, h01.y, h23.x, h23.y};
            const float wf[8] = {w0.x, w0.y, w0.z, w0.w, w1.x, w1.y, w1.z, w1.w};
#pragma unroll
            for (int c = 0; c < 8; ++c) {
                const unsigned long long ws = splat2(wf[c]);
#pragma unroll
                for (int rp = 0; rp < 4; ++rp) fma2(acc[rp][c], hp[rp], ws);
            }
        }
        __syncthreads();   // everyone done reading sH

        // ---- dump warp partials into sGp (= sH region) ----
        float* sGp = sH;   // [4][32][64]
#pragma unroll
        for (int c = 0; c < 8; ++c)
#pragma unroll
            for (int rp = 0; rp < 4; ++rp) {
                const float2 u = unpack2(acc[rp][c]);
                *(float2*)&sGp[wrp * 2048 + (cb + c) * 64 + rg + rp * 2] = u;
            }
        __syncthreads();

        // ---- reduce + elementwise + write h/out ----
        float* hnext = hbase + (size_t)((t + 1) & 1) * (H_ * B_);
#pragma unroll
        for (int it = 0; it < 4; ++it) {
            const int e   = it * 128 + tid;     // 0..511
            const int row = e >> 3;
            const int hj  = e & 7;
            const int len = sLen[row];
            const bool valid = (t < len);
            int pos;
            if (dir) pos = valid ? (len - 1 - t) : t;
            else     pos = t;

            const int j0 = hj, j1 = 8 + hj, j2 = 16 + hj, j3 = 24 + hj;
            float gi = sGp[j0 * 64 + row] + sGp[2048 + j0 * 64 + row]
                     + sGp[4096 + j0 * 64 + row] + sGp[6144 + j0 * 64 + row];
            float gf = sGp[j1 * 64 + row] + sGp[2048 + j1 * 64 + row]
                     + sGp[4096 + j1 * 64 + row] + sGp[6144 + j1 * 64 + row];
            float gg = sGp[j2 * 64 + row] + sGp[2048 + j2 * 64 + row]
                     + sGp[4096 + j2 * 64 + row] + sGp[6144 + j2 * 64 + row];
            float go = sGp[j3 * 64 + row] + sGp[2048 + j3 * 64 + row]
                     + sGp[4096 + j3 * 64 + row] + sGp[6144 + j3 * 64 + row];

            const size_t pb = ((size_t)row * T_ + pos) * H4_ + cg * 8 + hj;
            gi += pre[pb];
            gf += pre[pb + 512];
            gg += pre[pb + 1024];
            go += pre[pb + 1536];

            const float iv = sigmoidf_(gi);
            const float fv = sigmoidf_(gf);
            const float gv = tanhf(gg);
            const float ov = sigmoidf_(go);
            const float cn = fv * creg[it] + iv * gv;
            const float hn = ov * tanhf(cn);
            if (valid) { creg[it] = cn; hreg[it] = hn; }

            outBuf[((size_t)row * T_ + pos) * (2 * H_) + dir * H_ + cg * 8 + hj] =
                valid ? hn : 0.0f;
            __stcg(&hnext[(cg * 8 + hj) * 64 + row], hreg[it]);
        }

        // ---- grid barrier ----
        __threadfence();
        __syncthreads();
        if (tid == 0) {
            atomicAdd(&g_bar, 1u);
            const unsigned tgt = (unsigned)(t + 1) * gridDim.x;
            while (*(volatile unsigned*)&g_bar < tgt) { __nanosleep(32); }
        }
        __syncthreads();
    }
}

// ---------------- classifier: logits = out2 @ cls_w^T + cls_b ---------------
__global__ void __launch_bounds__(256, 1)
classifier_kernel(const float* __restrict__ clsW, const float* __restrict__ clsB,
                  float* __restrict__ out) {
    __shared__ __align__(16) float sX[8][1028];
    const int tid = threadIdx.x;
    const size_t r0 = (size_t)blockIdx.x * 8;
    const float* src = g_out2 + r0 * (2 * H_);
    for (int i = tid; i < 8 * 256; i += 256) {
        const int rr = i >> 8;
        const int kk = (i & 255) * 4;
        *(float4*)&sX[rr][kk] = *(const float4*)(src + (size_t)rr * 1024 + kk);
    }
    __syncthreads();
    for (int e = tid; e < 8 * TAGS_; e += 256) {
        const int r = e & 7;
        const int c = e >> 3;
        const float* w = clsW + (size_t)c * 1024;
        float s0 = 0.f, s1 = 0.f, s2 = 0.f, s3 = 0.f;
#pragma unroll 8
        for (int k = 0; k < 1024; k += 4) {
            const float4 a = *(const float4*)&sX[r][k];
            const float4 b = __ldg((const float4*)(w + k));
            s0 += a.x * b.x; s1 += a.y * b.y; s2 += a.z * b.z; s3 += a.w * b.w;
        }
        out[(r0 + r) * TAGS_ + c] = s0 + s1 + s2 + s3 + clsB[c];
    }
}

// ---------------- host launcher ---------------------------------------------
extern "C" void kernel_launch(void* const* d_in, const int* in_sizes, int n_in,
                              void* d_out, int out_size) {
    (void)in_sizes; (void)n_in; (void)out_size;
    const void*  x        = d_in[0];
    const void*  lengths  = d_in[1];
    const float* emb      = (const float*)d_in[2];
    const float* w_ih_f1  = (const float*)d_in[3];
    const float* w_hh_f1  = (const float*)d_in[4];
    const float* b_f1     = (const float*)d_in[5];
    const float* w_ih_b1  = (const float*)d_in[6];
    const float* w_hh_b1  = (const float*)d_in[7];
    const float* b_b1     = (const float*)d_in[8];
    const float* w_ih_f2  = (const float*)d_in[9];
    const float* w_hh_f2  = (const float*)d_in[10];
    const float* b_f2     = (const float*)d_in[11];
    const float* w_ih_b2  = (const float*)d_in[12];
    const float* w_hh_b2  = (const float*)d_in[13];
    const float* b_b2     = (const float*)d_in[14];
    const float* cls_w    = (const float*)d_in[15];
    const float* cls_b    = (const float*)d_in[16];
    float* out = (float*)d_out;

    float *pE, *pPF, *pPB, *pO1, *pO2;
    cudaGetSymbolAddress((void**)&pE,  g_e);
    cudaGetSymbolAddress((void**)&pPF, g_preF);
    cudaGetSymbolAddress((void**)&pPB, g_preB);
    cudaGetSymbolAddress((void**)&pO1, g_out1);
    cudaGetSymbolAddress((void**)&pO2, g_out2);

    cudaFuncSetAttribute(lstm_layer_kernel,
                         cudaFuncAttributeMaxDynamicSharedMemorySize, SMEM_BYTES);

    const int M = B_ * T_;
    const dim3 gemm_grid(H4_ / 128, M / 128);

    detect_kernel<<<1, 64>>>(x, lengths);
    gather_kernel<<<M, 64>>>(x, emb);
    init_state_kernel<<<256, 256>>>();

    sgemm_nt_bias<<<gemm_grid, 256>>>(pE, w_ih_f1, b_f1, pPF, M, H4_, E_);
    sgemm_nt_bias<<<gemm_grid, 256>>>(pE, w_ih_b1, b_b1, pPB, M, H4_, E_);
    lstm_layer_kernel<<<128, 128, SMEM_BYTES>>>(pPF, pPB, w_hh_f1, w_hh_b1, pO1);

    init_state_kernel<<<256, 256>>>();

    sgemm_nt_bias<<<gemm_grid, 256>>>(pO1, w_ih_f2, b_f2, pPF, M, H4_, 2 * H_);
    sgemm_nt_bias<<<gemm_grid, 256>>>(pO1, w_ih_b2, b_b2, pPB, M, H4_, 2 * H_);
    lstm_layer_kernel<<<128, 128, SMEM_BYTES>>>(pPF, pPB, w_hh_f2, w_hh_b2, pO2);

    classifier_kernel<<<M / 8, 256>>>(cls_w, cls_b, out);
}

// round 4
// speedup vs baseline: 1.6246x; 1.2919x over previous
#include <cuda_runtime.h>
#include <cstdint>
#include <cstdio>

#define B_    64
#define T_    256
#define E_    256
#define H_    512
#define H4_   2048
#define TAGS_ 50

#define SW_STRIDE 36
#define GP_J      66                     // sGp j-stride (bank spread)
#define SMEM_FLOATS (512 * SW_STRIDE + 512 * 64 + 64)
#define SMEM_BYTES  (SMEM_FLOATS * 4)

// ---------------- scratch ----------------------------------------------------
__device__ float g_e[B_ * T_ * E_];
__device__ float g_preF[(size_t)B_ * T_ * H4_];
__device__ float g_preB[(size_t)B_ * T_ * H4_];
__device__ float g_out1[(size_t)B_ * T_ * 2 * H_];
__device__ float g_out2[(size_t)B_ * T_ * 2 * H_];
__device__ float g_hF[2][H_ * B_];          // transposed: [k][row]
__device__ float g_hB[2][H_ * B_];
__device__ unsigned g_bar;
__device__ int g_is64;
__device__ int g_len[B_];

// ---------------- helpers ----------------------------------------------------
__device__ __forceinline__ float sig_fast(float x) {
    return __fdividef(1.0f, 1.0f + __expf(-x));
}
__device__ __forceinline__ float tanh_fast(float x) {
    const float e = __expf(-2.0f * x);
    return __fdividef(1.0f - e, 1.0f + e);
}
__device__ __forceinline__ unsigned long long splat2(float v) {
    unsigned long long r;
    asm("mov.b64 %0, {%1, %1};" : "=l"(r) : "f"(v));
    return r;
}
__device__ __forceinline__ void fma2(unsigned long long& d,
                                     unsigned long long a, unsigned long long b) {
    asm("fma.rn.f32x2 %0, %1, %2, %0;" : "+l"(d) : "l"(a), "l"(b));
}
__device__ __forceinline__ float2 unpack2(unsigned long long v) {
    float2 u;
    asm("mov.b64 {%0, %1}, %2;" : "=f"(u.x), "=f"(u.y) : "l"(v));
    return u;
}

// ---------------- dtype detect + lengths -------------------------------------
__global__ void detect_kernel(const void* x, const void* lengths) {
    __shared__ int s64;
    if (threadIdx.x == 0) {
        const int* xi = (const int*)x;
        int flag = 1;
        for (int i = 1; i <= 16; ++i)
            if (xi[2 * i + 1] != 0) flag = 0;
        g_is64 = flag;
        s64 = flag;
    }
    __syncthreads();
    if (threadIdx.x < B_) {
        int l = s64 ? (int)((const long long*)lengths)[threadIdx.x]
                    : ((const int*)lengths)[threadIdx.x];
        g_len[threadIdx.x] = l;
    }
}

// ---------------- embedding gather -------------------------------------------
__global__ void gather_kernel(const void* x, const float* __restrict__ emb) {
    const int row = blockIdx.x;
    long long idx = g_is64 ? ((const long long*)x)[row]
                           : (long long)((const int*)x)[row];
    const float4* src = (const float4*)(emb + (size_t)idx * E_);
    float4* dst = (float4*)(g_e + (size_t)row * E_);
    dst[threadIdx.x] = src[threadIdx.x];
}

// ---------------- init --------------------------------------------------------
__global__ void init_state_kernel() {
    int i = blockIdx.x * blockDim.x + threadIdx.x;
    const int n = 2 * B_ * H_;
    if (i < n) {
        ((float*)g_hF)[i] = 0.0f;
        ((float*)g_hB)[i] = 0.0f;
    }
    if (i == 0) g_bar = 0u;
}

// ---------------- fp32 SGEMM (f32x2): C = A @ W^T + bias ---------------------
__global__ void __launch_bounds__(256, 1)
sgemm_nt_bias(const float* __restrict__ A, const float* __restrict__ Bw,
              const float* __restrict__ bias, float* __restrict__ C,
              int M, int N, int K) {
    __shared__ __align__(16) float sA[8][128];
    __shared__ __align__(16) float sB[8][128];
    const int tid = threadIdx.x;
    const int bm = blockIdx.y * 128;
    const int bn = blockIdx.x * 128;
    const int lr = tid >> 1;
    const int lc = (tid & 1) * 4;
    const int tr = (tid >> 4) * 8;
    const int tc = (tid & 15) * 8;

    unsigned long long acc2[8][4];
#pragma unroll
    for (int i = 0; i < 8; ++i)
#pragma unroll
        for (int j = 0; j < 4; ++j) acc2[i][j] = 0ull;

    const float* Ap = A + (size_t)(bm + lr) * K + lc;
    const float* Bp = Bw + (size_t)(bn + lr) * K + lc;

    for (int k0 = 0; k0 < K; k0 += 8) {
        const float4 av = *(const float4*)(Ap + k0);
        const float4 bv = *(const float4*)(Bp + k0);
        __syncthreads();
        sA[lc + 0][lr] = av.x; sA[lc + 1][lr] = av.y;
        sA[lc + 2][lr] = av.z; sA[lc + 3][lr] = av.w;
        sB[lc + 0][lr] = bv.x; sB[lc + 1][lr] = bv.y;
        sB[lc + 2][lr] = bv.z; sB[lc + 3][lr] = bv.w;
        __syncthreads();
#pragma unroll
        for (int kk = 0; kk < 8; ++kk) {
            const float4 a0 = *(const float4*)&sA[kk][tr];
            const float4 a1 = *(const float4*)&sA[kk][tr + 4];
            const ulonglong2 b0 = *(const ulonglong2*)&sB[kk][tc];
            const ulonglong2 b1 = *(const ulonglong2*)&sB[kk][tc + 4];
            const unsigned long long bp[4] = {b0.x, b0.y, b1.x, b1.y};
            const float ra[8] = {a0.x, a0.y, a0.z, a0.w, a1.x, a1.y, a1.z, a1.w};
#pragma unroll
            for (int i = 0; i < 8; ++i) {
                const unsigned long long as = splat2(ra[i]);
#pragma unroll
                for (int j = 0; j < 4; ++j) fma2(acc2[i][j], as, bp[j]);
            }
        }
    }

    const float4 bb0 = *(const float4*)&bias[bn + tc];
    const float4 bb1 = *(const float4*)&bias[bn + tc + 4];
#pragma unroll
    for (int i = 0; i < 8; ++i) {
        const float2 c0 = unpack2(acc2[i][0]);
        const float2 c1 = unpack2(acc2[i][1]);
        const float2 c2 = unpack2(acc2[i][2]);
        const float2 c3 = unpack2(acc2[i][3]);
        float4 v0 = make_float4(c0.x + bb0.x, c0.y + bb0.y, c1.x + bb0.z, c1.y + bb0.w);
        float4 v1 = make_float4(c2.x + bb1.x, c2.y + bb1.y, c3.x + bb1.z, c3.y + bb1.w);
        float* cp = C + (size_t)(bm + tr + i) * N + bn + tc;
        *(float4*)cp = v0;
        *(float4*)(cp + 4) = v1;
    }
}

// ---------------- persistent BiLSTM layer ------------------------------------
// 128 CTAs x 256 threads. bx>>6 = dir, bx&63 = column group (8 h-cols, 32 gate
// cols). W_hh slice persistent in smem. 8 warps split K (64 each); each warp
// stages its OWN h k-slice (no CTA sync pre-GEMM). Microtile 16 rows x 4 cols,
// f32x2 FMAs (h row-pairs natural, only 4 splats/k). Partials -> padded smem,
// reduce + fast-activation elementwise with prefetched pre[]. Lean barrier.
__global__ void __launch_bounds__(256, 1)
lstm_layer_kernel(const float* __restrict__ preF, const float* __restrict__ preB,
                  const float* __restrict__ whF, const float* __restrict__ whB,
                  float* __restrict__ outBuf) {
    extern __shared__ __align__(16) float smem_[];
    float* sW = smem_;                          // [512][36]
    float* sH = smem_ + 512 * SW_STRIDE;        // [512][64]; reused as sGp[8][32][66]
    int* sLen = (int*)(smem_ + 512 * SW_STRIDE + 512 * 64);

    const int tid  = threadIdx.x;
    const int bx   = blockIdx.x;
    const int dir  = bx >> 6;
    const int cg   = bx & 63;
    const int lane = tid & 31;
    const int wrp  = tid >> 5;

    const float* __restrict__ pre = dir ? preB : preF;
    const float* __restrict__ W   = dir ? whB : whF;
    float* hbase = dir ? &g_hB[0][0] : &g_hF[0][0];

    if (tid < B_) sLen[tid] = g_len[tid];
    for (int idx = tid; idx < 32 * 512; idx += 256) {
        const int j = idx >> 9;
        const int k = idx & 511;
        const int gcol = (j >> 3) * 512 + cg * 8 + (j & 7);
        sW[k * SW_STRIDE + j] = W[(size_t)gcol * H_ + k];
    }
    __syncthreads();

    // GEMM mapping: 16 rows x 4 cols per lane
    const int rg = (lane >> 3) * 16;            // 0,16,32,48
    const int cb = (lane & 7) * 4;              // 0..28
    const int k0 = wrp * 64;

    // elementwise mapping: 2 elems/thread
    const int row0 = tid >> 3;                  // elem0 row (elem1 row = row0+32)
    const int hj   = tid & 7;

    float creg[2] = {0.f, 0.f};
    float hreg[2] = {0.f, 0.f};
    const int len0 = sLen[row0];
    const int len1 = sLen[row0 + 32];

    // prefetch pre for t=0
    float p0[4], p1[4];
    {
        const int pos0 = dir ? (len0 - 1) : 0;  // t=0 always valid (len>=1)
        const int pos1 = dir ? (len1 - 1) : 0;
        const size_t pb0 = ((size_t)row0 * T_ + pos0) * H4_ + cg * 8 + hj;
        const size_t pb1 = ((size_t)(row0 + 32) * T_ + pos1) * H4_ + cg * 8 + hj;
#pragma unroll
        for (int g = 0; g < 4; ++g) {
            p0[g] = __ldg(&pre[pb0 + g * 512]);
            p1[g] = __ldg(&pre[pb1 + g * 512]);
        }
    }

    for (int t = 0; t < T_; ++t) {
        // ---- stage this warp's h k-slice (16 KB) ----
        {
            const float4* src = (const float4*)(hbase + (size_t)(t & 1) * (H_ * B_));
            float4* dst = (float4*)sH;
            const int base = wrp * 1024;
#pragma unroll 8
            for (int i = 0; i < 32; ++i)
                dst[base + i * 32 + lane] = __ldcg(src + base + i * 32 + lane);
        }
        __syncwarp();

        // ---- GEMM: warp's K slice over full 64x32 tile ----
        unsigned long long acc[8][4];
#pragma unroll
        for (int rp = 0; rp < 8; ++rp)
#pragma unroll
            for (int c = 0; c < 4; ++c) acc[rp][c] = 0ull;

#pragma unroll 2
        for (int kk = 0; kk < 64; ++kk) {
            const int k = k0 + kk;
            const float* hp = &sH[k * 64 + rg];
            const ulonglong2 h01 = *(const ulonglong2*)(hp);
            const ulonglong2 h23 = *(const ulonglong2*)(hp + 4);
            const ulonglong2 h45 = *(const ulonglong2*)(hp + 8);
            const ulonglong2 h67 = *(const ulonglong2*)(hp + 12);
            const unsigned long long hpk[8] = {h01.x, h01.y, h23.x, h23.y,
                                               h45.x, h45.y, h67.x, h67.y};
            const float4 wv = *(const float4*)&sW[k * SW_STRIDE + cb];
            const float wf[4] = {wv.x, wv.y, wv.z, wv.w};
#pragma unroll
            for (int c = 0; c < 4; ++c) {
                const unsigned long long ws = splat2(wf[c]);
#pragma unroll
                for (int rp = 0; rp < 8; ++rp) fma2(acc[rp][c], hpk[rp], ws);
            }
        }
        __syncthreads();   // all warps done reading sH

        // ---- dump partials into sGp ----
        float* sGp = sH;   // [8][32][GP_J]
#pragma unroll
        for (int c = 0; c < 4; ++c)
#pragma unroll
            for (int rp = 0; rp < 8; ++rp) {
                const float2 u = unpack2(acc[rp][c]);
                *(float2*)&sGp[wrp * (32 * GP_J) + (cb + c) * GP_J + rg + 2 * rp] = u;
            }
        __syncthreads();

        // ---- reduce + elementwise ----
        float* hnext = hbase + (size_t)((t + 1) & 1) * (H_ * B_);
#pragma unroll
        for (int it = 0; it < 2; ++it) {
            const int row = row0 + it * 32;
            const int len = it ? len1 : len0;
            const float* pp = it ? p1 : p0;
            const bool valid = (t < len);
            const int pos = dir ? (valid ? (len - 1 - t) : t) : t;

            float gi = 0.f, gf = 0.f, gg = 0.f, go = 0.f;
#pragma unroll
            for (int w = 0; w < 8; ++w) {
                const float* gp = sGp + w * (32 * GP_J) + row;
                gi += gp[(hj)      * GP_J];
                gf += gp[(8 + hj)  * GP_J];
                gg += gp[(16 + hj) * GP_J];
                go += gp[(24 + hj) * GP_J];
            }
            gi += pp[0]; gf += pp[1]; gg += pp[2]; go += pp[3];

            const float iv = sig_fast(gi);
            const float fv = sig_fast(gf);
            const float gv = tanh_fast(gg);
            const float ov = sig_fast(go);
            const float cn = fv * creg[it] + iv * gv;
            const float hn = ov * tanh_fast(cn);
            if (valid) { creg[it] = cn; hreg[it] = hn; }

            outBuf[((size_t)row * T_ + pos) * (2 * H_) + dir * H_ + cg * 8 + hj] =
                valid ? hn : 0.0f;
            __stcg(&hnext[(cg * 8 + hj) * 64 + row], hreg[it]);
        }

        // ---- prefetch pre for t+1 (hidden under barrier + next GEMM) ----
        if (t + 1 < T_) {
            const int tn = t + 1;
            const bool v0 = (tn < len0), v1 = (tn < len1);
            const int pos0 = dir ? (v0 ? (len0 - 1 - tn) : tn) : tn;
            const int pos1 = dir ? (v1 ? (len1 - 1 - tn) : tn) : tn;
            const size_t pb0 = ((size_t)row0 * T_ + pos0) * H4_ + cg * 8 + hj;
            const size_t pb1 = ((size_t)(row0 + 32) * T_ + pos1) * H4_ + cg * 8 + hj;
#pragma unroll
            for (int g = 0; g < 4; ++g) {
                p0[g] = __ldg(&pre[pb0 + g * 512]);
                p1[g] = __ldg(&pre[pb1 + g * 512]);
            }
        }

        // ---- grid barrier (lean) ----
        __syncthreads();
        if (tid == 0) {
            __threadfence();
            atomicAdd(&g_bar, 1u);
            const unsigned tgt = (unsigned)(t + 1) * gridDim.x;
            unsigned v;
            do {
                asm volatile("ld.acquire.gpu.global.u32 %0, [%1];"
                             : "=r"(v) : "l"(&g_bar));
            } while (v < tgt);
        }
        __syncthreads();
    }
}

// ---------------- classifier --------------------------------------------------
__global__ void __launch_bounds__(256, 1)
classifier_kernel(const float* __restrict__ clsW, const float* __restrict__ clsB,
                  float* __restrict__ out) {
    __shared__ __align__(16) float sX[8][1028];
    const int tid = threadIdx.x;
    const size_t r0 = (size_t)blockIdx.x * 8;
    const float* src = g_out2 + r0 * (2 * H_);
    for (int i = tid; i < 8 * 256; i += 256) {
        const int rr = i >> 8;
        const int kk = (i & 255) * 4;
        *(float4*)&sX[rr][kk] = *(const float4*)(src + (size_t)rr * 1024 + kk);
    }
    __syncthreads();
    for (int e = tid; e < 8 * TAGS_; e += 256) {
        const int r = e & 7;
        const int c = e >> 3;
        const float* w = clsW + (size_t)c * 1024;
        float s0 = 0.f, s1 = 0.f, s2 = 0.f, s3 = 0.f;
#pragma unroll 8
        for (int k = 0; k < 1024; k += 4) {
            const float4 a = *(const float4*)&sX[r][k];
            const float4 b = __ldg((const float4*)(w + k));
            s0 += a.x * b.x; s1 += a.y * b.y; s2 += a.z * b.z; s3 += a.w * b.w;
        }
        out[(r0 + r) * TAGS_ + c] = s0 + s1 + s2 + s3 + clsB[c];
    }
}

// ---------------- host launcher -----------------------------------------------
extern "C" void kernel_launch(void* const* d_in, const int* in_sizes, int n_in,
                              void* d_out, int out_size) {
    (void)in_sizes; (void)n_in; (void)out_size;
    const void*  x        = d_in[0];
    const void*  lengths  = d_in[1];
    const float* emb      = (const float*)d_in[2];
    const float* w_ih_f1  = (const float*)d_in[3];
    const float* w_hh_f1  = (const float*)d_in[4];
    const float* b_f1     = (const float*)d_in[5];
    const float* w_ih_b1  = (const float*)d_in[6];
    const float* w_hh_b1  = (const float*)d_in[7];
    const float* b_b1     = (const float*)d_in[8];
    const float* w_ih_f2  = (const float*)d_in[9];
    const float* w_hh_f2  = (const float*)d_in[10];
    const float* b_f2     = (const float*)d_in[11];
    const float* w_ih_b2  = (const float*)d_in[12];
    const float* w_hh_b2  = (const float*)d_in[13];
    const float* b_b2     = (const float*)d_in[14];
    const float* cls_w    = (const float*)d_in[15];
    const float* cls_b    = (const float*)d_in[16];
    float* out = (float*)d_out;

    float *pE, *pPF, *pPB, *pO1, *pO2;
    cudaGetSymbolAddress((void**)&pE,  g_e);
    cudaGetSymbolAddress((void**)&pPF, g_preF);
    cudaGetSymbolAddress((void**)&pPB, g_preB);
    cudaGetSymbolAddress((void**)&pO1, g_out1);
    cudaGetSymbolAddress((void**)&pO2, g_out2);

    cudaFuncSetAttribute(lstm_layer_kernel,
                         cudaFuncAttributeMaxDynamicSharedMemorySize, SMEM_BYTES);

    const int M = B_ * T_;
    const dim3 gemm_grid(H4_ / 128, M / 128);

    detect_kernel<<<1, 64>>>(x, lengths);
    gather_kernel<<<M, 64>>>(x, emb);
    init_state_kernel<<<256, 256>>>();

    sgemm_nt_bias<<<gemm_grid, 256>>>(pE, w_ih_f1, b_f1, pPF, M, H4_, E_);
    sgemm_nt_bias<<<gemm_grid, 256>>>(pE, w_ih_b1, b_b1, pPB, M, H4_, E_);
    lstm_layer_kernel<<<128, 256, SMEM_BYTES>>>(pPF, pPB, w_hh_f1, w_hh_b1, pO1);

    init_state_kernel<<<256, 256>>>();

    sgemm_nt_bias<<<gemm_grid, 256>>>(pO1, w_ih_f2, b_f2, pPF, M, H4_, 2 * H_);
    sgemm_nt_bias<<<gemm_grid, 256>>>(pO1, w_ih_b2, b_b2, pPB, M, H4_, 2 * H_);
    lstm_layer_kernel<<<128, 256, SMEM_BYTES>>>(pPF, pPB, w_hh_f2, w_hh_b2, pO2);

    classifier_kernel<<<M / 8, 256>>>(cls_w, cls_b, out);
}

// round 5
// speedup vs baseline: 1.6729x; 1.0297x over previous
#include <cuda_runtime.h>
#include <cstdint>
#include <cstdio>

#define B_    64
#define T_    256
#define E_    256
#define H_    512
#define H4_   2048
#define TAGS_ 50

#define SW_STRIDE 36
#define GP_J      68                       // sGp col stride: reduce is conflict-free
#define SMEM_FLOATS (512 * SW_STRIDE + 512 * 64 + 64)
#define SMEM_BYTES  (SMEM_FLOATS * 4)

// ---------------- scratch ----------------------------------------------------
__device__ float g_e[B_ * T_ * E_];
__device__ float g_preF[(size_t)B_ * T_ * H4_];
__device__ float g_preB[(size_t)B_ * T_ * H4_];
__device__ float g_out1[(size_t)B_ * T_ * 2 * H_];
__device__ float g_out2[(size_t)B_ * T_ * 2 * H_];
__device__ float g_hF[2][H_ * B_];          // transposed: [k][row]
__device__ float g_hB[2][H_ * B_];
__device__ unsigned g_bar;
__device__ int g_is64;
__device__ int g_len[B_];

// ---------------- helpers ----------------------------------------------------
__device__ __forceinline__ float sig_fast(float x) {
    return __fdividef(1.0f, 1.0f + __expf(-x));
}
__device__ __forceinline__ float tanh_fast(float x) {
    const float e = __expf(-2.0f * x);
    return __fdividef(1.0f - e, 1.0f + e);
}
__device__ __forceinline__ unsigned long long splat2(float v) {
    unsigned long long r;
    asm("mov.b64 %0, {%1, %1};" : "=l"(r) : "f"(v));
    return r;
}
__device__ __forceinline__ void fma2(unsigned long long& d,
                                     unsigned long long a, unsigned long long b) {
    asm("fma.rn.f32x2 %0, %1, %2, %0;" : "+l"(d) : "l"(a), "l"(b));
}
__device__ __forceinline__ float2 unpack2(unsigned long long v) {
    float2 u;
    asm("mov.b64 {%0, %1}, %2;" : "=f"(u.x), "=f"(u.y) : "l"(v));
    return u;
}

// ---------------- dtype detect + lengths -------------------------------------
__global__ void detect_kernel(const void* x, const void* lengths) {
    __shared__ int s64;
    if (threadIdx.x == 0) {
        const int* xi = (const int*)x;
        int flag = 1;
        for (int i = 1; i <= 16; ++i)
            if (xi[2 * i + 1] != 0) flag = 0;
        g_is64 = flag;
        s64 = flag;
    }
    __syncthreads();
    if (threadIdx.x < B_) {
        int l = s64 ? (int)((const long long*)lengths)[threadIdx.x]
                    : ((const int*)lengths)[threadIdx.x];
        g_len[threadIdx.x] = l;
    }
}

// ---------------- embedding gather -------------------------------------------
__global__ void gather_kernel(const void* x, const float* __restrict__ emb) {
    const int row = blockIdx.x;
    long long idx = g_is64 ? ((const long long*)x)[row]
                           : (long long)((const int*)x)[row];
    const float4* src = (const float4*)(emb + (size_t)idx * E_);
    float4* dst = (float4*)(g_e + (size_t)row * E_);
    dst[threadIdx.x] = src[threadIdx.x];
}

// ---------------- init --------------------------------------------------------
__global__ void init_state_kernel() {
    int i = blockIdx.x * blockDim.x + threadIdx.x;
    const int n = 2 * B_ * H_;
    if (i < n) {
        ((float*)g_hF)[i] = 0.0f;
        ((float*)g_hB)[i] = 0.0f;
    }
    if (i == 0) g_bar = 0u;
}

// ---------------- fp32 SGEMM (f32x2, double-buffered): C = A @ W^T + bias ----
__global__ void __launch_bounds__(256, 2)
sgemm_nt_bias(const float* __restrict__ A, const float* __restrict__ Bw,
              const float* __restrict__ bias, float* __restrict__ C,
              int M, int N, int K) {
    __shared__ __align__(16) float sA[2][8][128];
    __shared__ __align__(16) float sB[2][8][128];
    const int tid = threadIdx.x;
    const int bm = blockIdx.y * 128;
    const int bn = blockIdx.x * 128;
    const int lr = tid >> 1;
    const int lc = (tid & 1) * 4;
    const int tr = (tid >> 4) * 8;
    const int tc = (tid & 15) * 8;

    unsigned long long acc2[8][4];
#pragma unroll
    for (int i = 0; i < 8; ++i)
#pragma unroll
        for (int j = 0; j < 4; ++j) acc2[i][j] = 0ull;

    const float* Ap = A + (size_t)(bm + lr) * K + lc;
    const float* Bp = Bw + (size_t)(bn + lr) * K + lc;
    const int NT = K >> 3;

    // preload tile 0 into smem[0]
    {
        const float4 av = *(const float4*)(Ap);
        const float4 bv = *(const float4*)(Bp);
        sA[0][lc + 0][lr] = av.x; sA[0][lc + 1][lr] = av.y;
        sA[0][lc + 2][lr] = av.z; sA[0][lc + 3][lr] = av.w;
        sB[0][lc + 0][lr] = bv.x; sB[0][lc + 1][lr] = bv.y;
        sB[0][lc + 2][lr] = bv.z; sB[0][lc + 3][lr] = bv.w;
    }
    // prefetch tile 1 into regs
    float4 avn = make_float4(0, 0, 0, 0), bvn = avn;
    if (NT > 1) { avn = *(const float4*)(Ap + 8); bvn = *(const float4*)(Bp + 8); }
    __syncthreads();

    for (int i = 0; i < NT; ++i) {
        const int buf = i & 1;
        if (i + 1 < NT) {                       // stage tile i+1 (other buffer)
            const int b2 = buf ^ 1;
            sA[b2][lc + 0][lr] = avn.x; sA[b2][lc + 1][lr] = avn.y;
            sA[b2][lc + 2][lr] = avn.z; sA[b2][lc + 3][lr] = avn.w;
            sB[b2][lc + 0][lr] = bvn.x; sB[b2][lc + 1][lr] = bvn.y;
            sB[b2][lc + 2][lr] = bvn.z; sB[b2][lc + 3][lr] = bvn.w;
        }
        if (i + 2 < NT) {                       // prefetch tile i+2
            avn = *(const float4*)(Ap + (size_t)(i + 2) * 8);
            bvn = *(const float4*)(Bp + (size_t)(i + 2) * 8);
        }
#pragma unroll
        for (int kk = 0; kk < 8; ++kk) {
            const float4 a0 = *(const float4*)&sA[buf][kk][tr];
            const float4 a1 = *(const float4*)&sA[buf][kk][tr + 4];
            const ulonglong2 b0 = *(const ulonglong2*)&sB[buf][kk][tc];
            const ulonglong2 b1 = *(const ulonglong2*)&sB[buf][kk][tc + 4];
            const unsigned long long bp[4] = {b0.x, b0.y, b1.x, b1.y};
            const float ra[8] = {a0.x, a0.y, a0.z, a0.w, a1.x, a1.y, a1.z, a1.w};
#pragma unroll
            for (int r = 0; r < 8; ++r) {
                const unsigned long long as = splat2(ra[r]);
#pragma unroll
                for (int j = 0; j < 4; ++j) fma2(acc2[r][j], as, bp[j]);
            }
        }
        __syncthreads();
    }

    const float4 bb0 = *(const float4*)&bias[bn + tc];
    const float4 bb1 = *(const float4*)&bias[bn + tc + 4];
#pragma unroll
    for (int i = 0; i < 8; ++i) {
        const float2 c0 = unpack2(acc2[i][0]);
        const float2 c1 = unpack2(acc2[i][1]);
        const float2 c2 = unpack2(acc2[i][2]);
        const float2 c3 = unpack2(acc2[i][3]);
        float4 v0 = make_float4(c0.x + bb0.x, c0.y + bb0.y, c1.x + bb0.z, c1.y + bb0.w);
        float4 v1 = make_float4(c2.x + bb1.x, c2.y + bb1.y, c3.x + bb1.z, c3.y + bb1.w);
        float* cp = C + (size_t)(bm + tr + i) * N + bn + tc;
        *(float4*)cp = v0;
        *(float4*)(cp + 4) = v1;
    }
}

// ---------------- persistent BiLSTM layer ------------------------------------
// 128 CTAs x 512 threads (4 warps/SMSP for latency hiding). bx>>6 = dir,
// bx&63 = column group (8 h-cols, 32 gate cols). W_hh slice persistent in smem.
// 16 warps = 8 K-slices x 2 N-halves; per-lane 8 rows x 4 cols, f32x2 FMAs.
// 8 partials per gate column -> padded smem (stride 68: conflict-free reduce),
// fused fast-activation elementwise (1 elem/thread), prefetched pre[],
// relaxed-poll grid barrier.
__global__ void __launch_bounds__(512, 1)
lstm_layer_kernel(const float* __restrict__ preF, const float* __restrict__ preB,
                  const float* __restrict__ whF, const float* __restrict__ whB,
                  float* __restrict__ outBuf) {
    extern __shared__ __align__(16) float smem_[];
    float* sW = smem_;                          // [512][36]
    float* sH = smem_ + 512 * SW_STRIDE;        // [512][64]; reused as sGp[8][32][68]
    int* sLen = (int*)(smem_ + 512 * SW_STRIDE + 512 * 64);

    const int tid  = threadIdx.x;
    const int bx   = blockIdx.x;
    const int dir  = bx >> 6;
    const int cg   = bx & 63;
    const int lane = tid & 31;
    const int wrp  = tid >> 5;
    const int ks   = wrp >> 1;                  // K slice 0..7
    const int ns   = wrp & 1;                   // N half 0..1

    const float* __restrict__ pre = dir ? preB : preF;
    const float* __restrict__ W   = dir ? whB : whF;
    float* hbase = dir ? &g_hB[0][0] : &g_hF[0][0];

    if (tid < B_) sLen[tid] = g_len[tid];
    for (int idx = tid; idx < 32 * 512; idx += 512) {
        const int j = idx >> 9;
        const int k = idx & 511;
        const int gcol = (j >> 3) * 512 + cg * 8 + (j & 7);
        sW[k * SW_STRIDE + j] = W[(size_t)gcol * H_ + k];
    }
    __syncthreads();

    // GEMM mapping: 8 rows x 4 cols per lane; warp covers 64 rows x 16 cols, 64 k
    const int rg = (lane >> 2) * 8;             // 0,8,...,56
    const int cb = ns * 16 + (lane & 3) * 4;    // gate col base
    const int kbase = ks * 64;

    // elementwise mapping: 1 elem/thread
    const int row = tid >> 3;                   // 0..63
    const int hj  = tid & 7;
    const int len = sLen[row];

    float creg = 0.f, hreg = 0.f;

    // prefetch pre for t=0 (always valid: len >= 1)
    float p[4];
    {
        const int pos = dir ? (len - 1) : 0;
        const size_t pb = ((size_t)row * T_ + pos) * H4_ + cg * 8 + hj;
#pragma unroll
        for (int g = 0; g < 4; ++g) p[g] = __ldg(&pre[pb + g * 512]);
    }

    for (int t = 0; t < T_; ++t) {
        // ---- stage h: warp wrp copies k in [wrp*32, wrp*32+32) ----
        {
            const float4* src = (const float4*)(hbase + (size_t)(t & 1) * (H_ * B_));
            float4* dst = (float4*)sH;
            const int base = wrp * 512;
#pragma unroll
            for (int i = 0; i < 16; ++i)
                dst[base + i * 32 + lane] = __ldcg(src + base + i * 32 + lane);
        }
        __syncthreads();

        // ---- GEMM: warp's 64-k slice over 64 rows x 16 cols ----
        unsigned long long acc[4][4];
#pragma unroll
        for (int rp = 0; rp < 4; ++rp)
#pragma unroll
            for (int c = 0; c < 4; ++c) acc[rp][c] = 0ull;

#pragma unroll 4
        for (int kk = 0; kk < 64; ++kk) {
            const int k = kbase + kk;
            const float* hp = &sH[k * 64 + rg];
            const ulonglong2 h01 = *(const ulonglong2*)(hp);
            const ulonglong2 h23 = *(const ulonglong2*)(hp + 4);
            const unsigned long long hpk[4] = {h01.x, h01.y, h23.x, h23.y};
            const float4 wv = *(const float4*)&sW[k * SW_STRIDE + cb];
            const float wf[4] = {wv.x, wv.y, wv.z, wv.w};
#pragma unroll
            for (int c = 0; c < 4; ++c) {
                const unsigned long long ws = splat2(wf[c]);
#pragma unroll
                for (int rp = 0; rp < 4; ++rp) fma2(acc[rp][c], hpk[rp], ws);
            }
        }
        __syncthreads();   // all warps done reading sH

        // ---- dump partials: sGp[ks][col][row] ----
        float* sGp = sH;   // [8][32][GP_J]
#pragma unroll
        for (int c = 0; c < 4; ++c)
#pragma unroll
            for (int rp = 0; rp < 4; ++rp) {
                const float2 u = unpack2(acc[rp][c]);
                *(float2*)&sGp[ks * (32 * GP_J) + (cb + c) * GP_J + rg + 2 * rp] = u;
            }
        __syncthreads();

        // ---- reduce + elementwise (1 elem/thread) ----
        float* hnext = hbase + (size_t)((t + 1) & 1) * (H_ * B_);
        {
            const bool valid = (t < len);
            const int pos = dir ? (valid ? (len - 1 - t) : t) : t;

            float gi = 0.f, gf = 0.f, gg = 0.f, go = 0.f;
#pragma unroll
            for (int w = 0; w < 8; ++w) {
                const float* gp = sGp + w * (32 * GP_J) + row;
                gi += gp[(hj)      * GP_J];
                gf += gp[(8 + hj)  * GP_J];
                gg += gp[(16 + hj) * GP_J];
                go += gp[(24 + hj) * GP_J];
            }
            gi += p[0]; gf += p[1]; gg += p[2]; go += p[3];

            const float iv = sig_fast(gi);
            const float fv = sig_fast(gf);
            const float gv = tanh_fast(gg);
            const float ov = sig_fast(go);
            const float cn = fv * creg + iv * gv;
            const float hn = ov * tanh_fast(cn);
            if (valid) { creg = cn; hreg = hn; }

            outBuf[((size_t)row * T_ + pos) * (2 * H_) + dir * H_ + cg * 8 + hj] =
                valid ? hn : 0.0f;
            __stcg(&hnext[(cg * 8 + hj) * 64 + row], hreg);
        }

        // ---- prefetch pre for t+1 (lands under barrier + next stage/GEMM) ----
        if (t + 1 < T_) {
            const int tn = t + 1;
            const bool v = (tn < len);
            const int pos = dir ? (v ? (len - 1 - tn) : tn) : tn;
            const size_t pb = ((size_t)row * T_ + pos) * H4_ + cg * 8 + hj;
#pragma unroll
            for (int g = 0; g < 4; ++g) p[g] = __ldg(&pre[pb + g * 512]);
        }

        // ---- grid barrier: release-arrive, relaxed poll, acquire on exit ----
        __syncthreads();
        if (tid == 0) {
            __threadfence();                    // release h stores
            atomicAdd(&g_bar, 1u);
            const unsigned tgt = (unsigned)(t + 1) * gridDim.x;
            unsigned v;
            do {
                asm volatile("ld.relaxed.gpu.global.u32 %0, [%1];"
                             : "=r"(v) : "l"(&g_bar));
            } while (v < tgt);
            asm volatile("fence.acq_rel.gpu;" ::: "memory");
        }
        __syncthreads();
    }
}

// ---------------- classifier --------------------------------------------------
__global__ void __launch_bounds__(256, 1)
classifier_kernel(const float* __restrict__ clsW, const float* __restrict__ clsB,
                  float* __restrict__ out) {
    __shared__ __align__(16) float sX[8][1028];
    const int tid = threadIdx.x;
    const size_t r0 = (size_t)blockIdx.x * 8;
    const float* src = g_out2 + r0 * (2 * H_);
    for (int i = tid; i < 8 * 256; i += 256) {
        const int rr = i >> 8;
        const int kk = (i & 255) * 4;
        *(float4*)&sX[rr][kk] = *(const float4*)(src + (size_t)rr * 1024 + kk);
    }
    __syncthreads();
    for (int e = tid; e < 8 * TAGS_; e += 256) {
        const int r = e & 7;
        const int c = e >> 3;
        const float* w = clsW + (size_t)c * 1024;
        float s0 = 0.f, s1 = 0.f, s2 = 0.f, s3 = 0.f;
#pragma unroll 8
        for (int k = 0; k < 1024; k += 4) {
            const float4 a = *(const float4*)&sX[r][k];
            const float4 b = __ldg((const float4*)(w + k));
            s0 += a.x * b.x; s1 += a.y * b.y; s2 += a.z * b.z; s3 += a.w * b.w;
        }
        out[(r0 + r) * TAGS_ + c] = s0 + s1 + s2 + s3 + clsB[c];
    }
}

// ---------------- host launcher -----------------------------------------------
extern "C" void kernel_launch(void* const* d_in, const int* in_sizes, int n_in,
                              void* d_out, int out_size) {
    (void)in_sizes; (void)n_in; (void)out_size;
    const void*  x        = d_in[0];
    const void*  lengths  = d_in[1];
    const float* emb      = (const float*)d_in[2];
    const float* w_ih_f1  = (const float*)d_in[3];
    const float* w_hh_f1  = (const float*)d_in[4];
    const float* b_f1     = (const float*)d_in[5];
    const float* w_ih_b1  = (const float*)d_in[6];
    const float* w_hh_b1  = (const float*)d_in[7];
    const float* b_b1     = (const float*)d_in[8];
    const float* w_ih_f2  = (const float*)d_in[9];
    const float* w_hh_f2  = (const float*)d_in[10];
    const float* b_f2     = (const float*)d_in[11];
    const float* w_ih_b2  = (const float*)d_in[12];
    const float* w_hh_b2  = (const float*)d_in[13];
    const float* b_b2     = (const float*)d_in[14];
    const float* cls_w    = (const float*)d_in[15];
    const float* cls_b    = (const float*)d_in[16];
    float* out = (float*)d_out;

    float *pE, *pPF, *pPB, *pO1, *pO2;
    cudaGetSymbolAddress((void**)&pE,  g_e);
    cudaGetSymbolAddress((void**)&pPF, g_preF);
    cudaGetSymbolAddress((void**)&pPB, g_preB);
    cudaGetSymbolAddress((void**)&pO1, g_out1);
    cudaGetSymbolAddress((void**)&pO2, g_out2);

    cudaFuncSetAttribute(lstm_layer_kernel,
                         cudaFuncAttributeMaxDynamicSharedMemorySize, SMEM_BYTES);

    const int M = B_ * T_;
    const dim3 gemm_grid(H4_ / 128, M / 128);

    detect_kernel<<<1, 64>>>(x, lengths);
    gather_kernel<<<M, 64>>>(x, emb);
    init_state_kernel<<<256, 256>>>();

    sgemm_nt_bias<<<gemm_grid, 256>>>(pE, w_ih_f1, b_f1, pPF, M, H4_, E_);
    sgemm_nt_bias<<<gemm_grid, 256>>>(pE, w_ih_b1, b_b1, pPB, M, H4_, E_);
    lstm_layer_kernel<<<128, 512, SMEM_BYTES>>>(pPF, pPB, w_hh_f1, w_hh_b1, pO1);

    init_state_kernel<<<256, 256>>>();

    sgemm_nt_bias<<<gemm_grid, 256>>>(pO1, w_ih_f2, b_f2, pPF, M, H4_, 2 * H_);
    sgemm_nt_bias<<<gemm_grid, 256>>>(pO1, w_ih_b2, b_b2, pPB, M, H4_, 2 * H_);
    lstm_layer_kernel<<<128, 512, SMEM_BYTES>>>(pPF, pPB, w_hh_f2, w_hh_b2, pO2);

    classifier_kernel<<<M / 8, 256>>>(cls_w, cls_b, out);
}

// round 6
// speedup vs baseline: 2.7610x; 1.6504x over previous
#include <cuda_runtime.h>
#include <cstdint>
#include <cstdio>

#define B_    64
#define T_    256
#define E_    256
#define H_    512
#define H4_   2048
#define TAGS_ 50

#define GP_J  68                         // split-K partial col stride (conflict-free)
// lstm smem: sW(tf32) 512*32 + sH 512*64 + lens
#define LSTM_SMEM_FLOATS (512 * 32 + 512 * 64 + 64)
#define LSTM_SMEM_BYTES  (LSTM_SMEM_FLOATS * 4)

// ---------------- scratch ----------------------------------------------------
__device__ float g_e[B_ * T_ * E_];
__device__ float g_preF[(size_t)B_ * T_ * H4_];
__device__ float g_preB[(size_t)B_ * T_ * H4_];
__device__ float g_out1[(size_t)B_ * T_ * 2 * H_];
__device__ float g_out2[(size_t)B_ * T_ * 2 * H_];
__device__ float g_hF[2][H_ * B_];          // transposed: [k][row], tf32-rounded
__device__ float g_hB[2][H_ * B_];
__device__ unsigned g_bar;
__device__ int g_is64;
__device__ int g_len[B_];

// ---------------- helpers ----------------------------------------------------
__device__ __forceinline__ float sig_fast(float x) {
    return __fdividef(1.0f, 1.0f + __expf(-x));
}
__device__ __forceinline__ float tanh_fast(float x) {
    const float e = __expf(-2.0f * x);
    return __fdividef(1.0f - e, 1.0f + e);
}
__device__ __forceinline__ float to_tf32(float x) {
    float r;
    asm("cvt.rna.tf32.f32 %0, %1;" : "=f"(r) : "f"(x));
    return r;
}
// D(16x8,f32) += A(16x8,tf32,row) * B(8x8,tf32,col)
__device__ __forceinline__ void mma_tf32(float d[4], const unsigned a[4],
                                         const unsigned b[2]) {
    asm volatile(
        "mma.sync.aligned.m16n8k8.row.col.f32.tf32.tf32.f32 "
        "{%0,%1,%2,%3}, {%4,%5,%6,%7}, {%8,%9}, {%0,%1,%2,%3};"
        : "+f"(d[0]), "+f"(d[1]), "+f"(d[2]), "+f"(d[3])
        : "r"(a[0]), "r"(a[1]), "r"(a[2]), "r"(a[3]), "r"(b[0]), "r"(b[1]));
}

// ---------------- dtype detect + lengths -------------------------------------
__global__ void detect_kernel(const void* x, const void* lengths) {
    __shared__ int s64;
    if (threadIdx.x == 0) {
        const int* xi = (const int*)x;
        int flag = 1;
        for (int i = 1; i <= 16; ++i)
            if (xi[2 * i + 1] != 0) flag = 0;
        g_is64 = flag;
        s64 = flag;
    }
    __syncthreads();
    if (threadIdx.x < B_) {
        int l = s64 ? (int)((const long long*)lengths)[threadIdx.x]
                    : ((const int*)lengths)[threadIdx.x];
        g_len[threadIdx.x] = l;
    }
}

// ---------------- embedding gather -------------------------------------------
__global__ void gather_kernel(const void* x, const float* __restrict__ emb) {
    const int row = blockIdx.x;
    long long idx = g_is64 ? ((const long long*)x)[row]
                           : (long long)((const int*)x)[row];
    const float4* src = (const float4*)(emb + (size_t)idx * E_);
    float4* dst = (float4*)(g_e + (size_t)row * E_);
    dst[threadIdx.x] = src[threadIdx.x];
}

// ---------------- init --------------------------------------------------------
__global__ void init_state_kernel() {
    int i = blockIdx.x * blockDim.x + threadIdx.x;
    const int n = 2 * B_ * H_;
    if (i < n) {
        ((float*)g_hF)[i] = 0.0f;
        ((float*)g_hB)[i] = 0.0f;
    }
    if (i == 0) g_bar = 0u;
}

// ---------------- tf32 MMA pre-GEMM: C[M,2048] = A[M,K] @ W[2048,K]^T + bias --
// CTA tile 128x64, 8 warps (4m x 2n grid of 32x32 warp tiles), k-chunk 16,
// double-buffered XOR-swizzled smem (conflict-free fragment loads).
__global__ void __launch_bounds__(256, 2)
mma_pre_gemm(const float* __restrict__ A, const float* __restrict__ W,
             const float* __restrict__ bias, float* __restrict__ C, int K) {
    __shared__ __align__(16) unsigned sA[2][16 * 128];
    __shared__ __align__(16) unsigned sB[2][16 * 64];
    const int tid  = threadIdx.x;
    const int lane = tid & 31;
    const int wrp  = tid >> 5;
    const int tg   = lane >> 2;
    const int tk   = lane & 3;
    const int bm = blockIdx.y * 128;
    const int bn = blockIdx.x * 64;
    const int wm = (wrp >> 1) * 32;
    const int wn = (wrp & 1) * 32;

    // loader mapping
    const int am  = tid >> 1;             // 0..127
    const int ak  = (tid & 1) * 8;        // 0 or 8
    const int bnl = tid & 63;             // 0..63
    const int bk  = (tid >> 6) * 4;       // 0,4,8,12

    const float* Ap = A + (size_t)(bm + am) * K + ak;
    const float* Bp = W + (size_t)(bn + bnl) * K + bk;

    float d[2][4][4];
#pragma unroll
    for (int mi = 0; mi < 2; ++mi)
#pragma unroll
        for (int ni = 0; ni < 4; ++ni)
#pragma unroll
            for (int q = 0; q < 4; ++q) d[mi][ni][q] = 0.0f;

    const int NT = K >> 4;

#define STAGE_A(buf, v0, v1)                                                    \
    do {                                                                        \
        const float va[8] = {(v0).x, (v0).y, (v0).z, (v0).w,                   \
                             (v1).x, (v1).y, (v1).z, (v1).w};                  \
        _Pragma("unroll")                                                       \
        for (int i = 0; i < 8; ++i) {                                           \
            const int kk = ak + i;                                              \
            sA[buf][kk * 128 + (am ^ ((kk & 3) << 3))] =                        \
                __float_as_uint(to_tf32(va[i]));                                \
        }                                                                       \
    } while (0)
#define STAGE_B(buf, v0)                                                        \
    do {                                                                        \
        const float vb[4] = {(v0).x, (v0).y, (v0).z, (v0).w};                  \
        _Pragma("unroll")                                                       \
        for (int i = 0; i < 4; ++i) {                                           \
            const int kk = bk + i;                                              \
            sB[buf][kk * 64 + (bnl ^ ((kk & 3) << 3))] =                        \
                __float_as_uint(to_tf32(vb[i]));                                \
        }                                                                       \
    } while (0)

    {   // chunk 0 direct
        const float4 a0 = *(const float4*)(Ap);
        const float4 a1 = *(const float4*)(Ap + 4);
        const float4 b0 = *(const float4*)(Bp);
        STAGE_A(0, a0, a1);
        STAGE_B(0, b0);
    }
    float4 pa0 = make_float4(0, 0, 0, 0), pa1 = pa0, pb0 = pa0;
    if (NT > 1) {
        pa0 = *(const float4*)(Ap + 16);
        pa1 = *(const float4*)(Ap + 20);
        pb0 = *(const float4*)(Bp + 16);
    }
    __syncthreads();

    for (int i = 0; i < NT; ++i) {
        const int buf = i & 1;
        if (i + 1 < NT) { STAGE_A(buf ^ 1, pa0, pa1); STAGE_B(buf ^ 1, pb0); }
        if (i + 2 < NT) {
            pa0 = *(const float4*)(Ap + (size_t)(i + 2) * 16);
            pa1 = *(const float4*)(Ap + (size_t)(i + 2) * 16 + 4);
            pb0 = *(const float4*)(Bp + (size_t)(i + 2) * 16);
        }
#pragma unroll
        for (int ks8 = 0; ks8 < 2; ++ks8) {
            const int kb = ks8 * 8;
            unsigned af[2][4], bf[4][2];
#pragma unroll
            for (int mi = 0; mi < 2; ++mi) {
                const int rb = wm + mi * 16;
                const int sw = tk << 3;
                af[mi][0] = sA[buf][(kb + tk) * 128 + ((rb + tg) ^ sw)];
                af[mi][1] = sA[buf][(kb + tk) * 128 + ((rb + tg + 8) ^ sw)];
                af[mi][2] = sA[buf][(kb + tk + 4) * 128 + ((rb + tg) ^ sw)];
                af[mi][3] = sA[buf][(kb + tk + 4) * 128 + ((rb + tg + 8) ^ sw)];
            }
#pragma unroll
            for (int ni = 0; ni < 4; ++ni) {
                const int nb = wn + ni * 8;
                const int sw = tk << 3;
                bf[ni][0] = sB[buf][(kb + tk) * 64 + ((nb + tg) ^ sw)];
                bf[ni][1] = sB[buf][(kb + tk + 4) * 64 + ((nb + tg) ^ sw)];
            }
#pragma unroll
            for (int mi = 0; mi < 2; ++mi)
#pragma unroll
                for (int ni = 0; ni < 4; ++ni)
                    mma_tf32(d[mi][ni], af[mi], bf[ni]);
        }
        __syncthreads();
    }
#undef STAGE_A
#undef STAGE_B

#pragma unroll
    for (int mi = 0; mi < 2; ++mi) {
        const int r0 = bm + wm + mi * 16 + tg;
#pragma unroll
        for (int ni = 0; ni < 4; ++ni) {
            const int col = bn + wn + ni * 8 + tk * 2;
            const float2 bb = *(const float2*)&bias[col];
            *(float2*)&C[(size_t)r0 * H4_ + col] =
                make_float2(d[mi][ni][0] + bb.x, d[mi][ni][1] + bb.y);
            *(float2*)&C[(size_t)(r0 + 8) * H4_ + col] =
                make_float2(d[mi][ni][2] + bb.x, d[mi][ni][3] + bb.y);
        }
    }
}

// ---------------- persistent BiLSTM layer (tf32 MMA recurrence) ---------------
// 128 CTAs x 512 threads. bx>>6 = dir, bx&63 = column group (8 h-cols, 32 gate
// cols). W_hh slice tf32 in smem (XOR swizzle, loaded once). Each step: stage
// tf32 h [k][m] -> smem; 16 warps (8 K-slices x 2 N-halves) run m64n16k64 tiles
// of m16n8k8 tf32 MMA; split-K partials reduced via smem; fused fast-activation
// elementwise; relaxed-poll grid barrier.
__global__ void __launch_bounds__(512, 1)
lstm_layer_kernel(const float* __restrict__ preF, const float* __restrict__ preB,
                  const float* __restrict__ whF, const float* __restrict__ whB,
                  float* __restrict__ outBuf) {
    extern __shared__ __align__(16) float smem_[];
    float* sW = smem_;                          // [512][32] tf32 bits
    float* sH = smem_ + 512 * 32;               // [512][64]; reused as sGp[8][32][68]
    int* sLen = (int*)(smem_ + 512 * 32 + 512 * 64);
    unsigned* uW = (unsigned*)sW;
    unsigned* uH = (unsigned*)sH;

    const int tid  = threadIdx.x;
    const int bx   = blockIdx.x;
    const int dir  = bx >> 6;
    const int cg   = bx & 63;
    const int lane = tid & 31;
    const int wrp  = tid >> 5;
    const int tg   = lane >> 2;
    const int tk   = lane & 3;
    const int ks   = wrp >> 1;                  // K slice 0..7 (64 k each)
    const int ns   = wrp & 1;                   // N half (16 gate cols)

    const float* __restrict__ pre = dir ? preB : preF;
    const float* __restrict__ W   = dir ? whB : whF;
    float* hbase = dir ? &g_hB[0][0] : &g_hF[0][0];

    if (tid < B_) sLen[tid] = g_len[tid];
    // W_hh slice -> smem as tf32 [k][n] swizzled (coalesced in k)
    for (int idx = tid; idx < 32 * 512; idx += 512) {
        const int j = idx >> 9;                 // gate col 0..31
        const int k = idx & 511;
        const int gcol = (j >> 3) * 512 + cg * 8 + (j & 7);
        sW[k * 32 + (j ^ ((k & 3) << 3))] = to_tf32(W[(size_t)gcol * H_ + k]);
    }
    __syncthreads();

    // elementwise mapping: 1 elem/thread
    const int row = tid >> 3;                   // 0..63
    const int hj  = tid & 7;
    const int len = sLen[row];

    float creg = 0.f, hreg = 0.f;

    // prefetch pre for t=0 (always valid: len >= 1)
    float p[4];
    {
        const int pos = dir ? (len - 1) : 0;
        const size_t pb = ((size_t)row * T_ + pos) * H4_ + cg * 8 + hj;
#pragma unroll
        for (int g = 0; g < 4; ++g) p[g] = __ldg(&pre[pb + g * 512]);
    }

    for (int t = 0; t < T_; ++t) {
        // ---- stage h: [k][m] global -> swizzled smem (128 KB) ----
        {
            const float4* src =
                (const float4*)(hbase + (size_t)(t & 1) * (H_ * B_));
#pragma unroll
            for (int i = tid; i < 8192; i += 512) {
                const int k  = i >> 4;
                const int mq = (i & 15) << 2;
                const float4 v = __ldcg(src + i);
                *(float4*)&sH[k * 64 + (mq ^ ((k & 3) << 3))] = v;
            }
        }
        __syncthreads();

        // ---- MMA: warp (ks, ns): m64 n16 k64 ----
        float d[4][2][4];
#pragma unroll
        for (int mi = 0; mi < 4; ++mi)
#pragma unroll
            for (int ni = 0; ni < 2; ++ni)
#pragma unroll
                for (int q = 0; q < 4; ++q) d[mi][ni][q] = 0.0f;

#pragma unroll
        for (int kc = 0; kc < 8; ++kc) {
            const int kb = ks * 64 + kc * 8;
            const int sw = tk << 3;
            unsigned af[4][4], bf[2][2];
#pragma unroll
            for (int mi = 0; mi < 4; ++mi) {
                const int rb = mi * 16;
                af[mi][0] = uH[(kb + tk) * 64 + ((rb + tg) ^ sw)];
                af[mi][1] = uH[(kb + tk) * 64 + ((rb + tg + 8) ^ sw)];
                af[mi][2] = uH[(kb + tk + 4) * 64 + ((rb + tg) ^ sw)];
                af[mi][3] = uH[(kb + tk + 4) * 64 + ((rb + tg + 8) ^ sw)];
            }
#pragma unroll
            for (int ni = 0; ni < 2; ++ni) {
                const int nb = ns * 16 + ni * 8;
                bf[ni][0] = uW[(kb + tk) * 32 + ((nb + tg) ^ sw)];
                bf[ni][1] = uW[(kb + tk + 4) * 32 + ((nb + tg) ^ sw)];
            }
#pragma unroll
            for (int mi = 0; mi < 4; ++mi)
#pragma unroll
                for (int ni = 0; ni < 2; ++ni)
                    mma_tf32(d[mi][ni], af[mi], bf[ni]);
        }
        __syncthreads();   // all warps done reading sH

        // ---- dump split-K partials: sGp[ks][col][row] ----
        float* sGp = sH;   // [8][32][GP_J]
        {
            float* g = sGp + ks * (32 * GP_J);
#pragma unroll
            for (int mi = 0; mi < 4; ++mi) {
                const int mb = mi * 16 + tg;
#pragma unroll
                for (int ni = 0; ni < 2; ++ni) {
                    const int nb = ns * 16 + ni * 8 + tk * 2;
                    g[nb * GP_J + mb]           = d[mi][ni][0];
                    g[(nb + 1) * GP_J + mb]     = d[mi][ni][1];
                    g[nb * GP_J + mb + 8]       = d[mi][ni][2];
                    g[(nb + 1) * GP_J + mb + 8] = d[mi][ni][3];
                }
            }
        }
        __syncthreads();

        // ---- reduce + elementwise (1 elem/thread) ----
        float* hnext = hbase + (size_t)((t + 1) & 1) * (H_ * B_);
        {
            const bool valid = (t < len);
            const int pos = dir ? (valid ? (len - 1 - t) : t) : t;

            float gi = 0.f, gf = 0.f, gg = 0.f, go = 0.f;
#pragma unroll
            for (int w = 0; w < 8; ++w) {
                const float* gp = sGp + w * (32 * GP_J) + row;
                gi += gp[(hj)      * GP_J];
                gf += gp[(8 + hj)  * GP_J];
                gg += gp[(16 + hj) * GP_J];
                go += gp[(24 + hj) * GP_J];
            }
            gi += p[0]; gf += p[1]; gg += p[2]; go += p[3];

            const float iv = sig_fast(gi);
            const float fv = sig_fast(gf);
            const float gv = tanh_fast(gg);
            const float ov = sig_fast(go);
            const float cn = fv * creg + iv * gv;
            const float hn = ov * tanh_fast(cn);
            if (valid) { creg = cn; hreg = hn; }

            outBuf[((size_t)row * T_ + pos) * (2 * H_) + dir * H_ + cg * 8 + hj] =
                valid ? hn : 0.0f;
            __stcg(&hnext[(cg * 8 + hj) * 64 + row], to_tf32(hreg));
        }

        // ---- prefetch pre for t+1 ----
        if (t + 1 < T_) {
            const int tn = t + 1;
            const bool v = (tn < len);
            const int pos = dir ? (v ? (len - 1 - tn) : tn) : tn;
            const size_t pb = ((size_t)row * T_ + pos) * H4_ + cg * 8 + hj;
#pragma unroll
            for (int g = 0; g < 4; ++g) p[g] = __ldg(&pre[pb + g * 512]);
        }

        // ---- grid barrier: release-arrive, relaxed poll ----
        __syncthreads();
        if (tid == 0) {
            __threadfence();
            atomicAdd(&g_bar, 1u);
            const unsigned tgt = (unsigned)(t + 1) * gridDim.x;
            unsigned v;
            do {
                asm volatile("ld.relaxed.gpu.global.u32 %0, [%1];"
                             : "=r"(v) : "l"(&g_bar));
            } while (v < tgt);
            asm volatile("fence.acq_rel.gpu;" ::: "memory");
        }
        __syncthreads();
    }
}

// ---------------- classifier --------------------------------------------------
__global__ void __launch_bounds__(256, 1)
classifier_kernel(const float* __restrict__ clsW, const float* __restrict__ clsB,
                  float* __restrict__ out) {
    __shared__ __align__(16) float sX[8][1028];
    const int tid = threadIdx.x;
    const size_t r0 = (size_t)blockIdx.x * 8;
    const float* src = g_out2 + r0 * (2 * H_);
    for (int i = tid; i < 8 * 256; i += 256) {
        const int rr = i >> 8;
        const int kk = (i & 255) * 4;
        *(float4*)&sX[rr][kk] = *(const float4*)(src + (size_t)rr * 1024 + kk);
    }
    __syncthreads();
    for (int e = tid; e < 8 * TAGS_; e += 256) {
        const int r = e & 7;
        const int c = e >> 3;
        const float* w = clsW + (size_t)c * 1024;
        float s0 = 0.f, s1 = 0.f, s2 = 0.f, s3 = 0.f;
#pragma unroll 8
        for (int k = 0; k < 1024; k += 4) {
            const float4 a = *(const float4*)&sX[r][k];
            const float4 b = __ldg((const float4*)(w + k));
            s0 += a.x * b.x; s1 += a.y * b.y; s2 += a.z * b.z; s3 += a.w * b.w;
        }
        out[(r0 + r) * TAGS_ + c] = s0 + s1 + s2 + s3 + clsB[c];
    }
}

// ---------------- host launcher -----------------------------------------------
extern "C" void kernel_launch(void* const* d_in, const int* in_sizes, int n_in,
                              void* d_out, int out_size) {
    (void)in_sizes; (void)n_in; (void)out_size;
    const void*  x        = d_in[0];
    const void*  lengths  = d_in[1];
    const float* emb      = (const float*)d_in[2];
    const float* w_ih_f1  = (const float*)d_in[3];
    const float* w_hh_f1  = (const float*)d_in[4];
    const float* b_f1     = (const float*)d_in[5];
    const float* w_ih_b1  = (const float*)d_in[6];
    const float* w_hh_b1  = (const float*)d_in[7];
    const float* b_b1     = (const float*)d_in[8];
    const float* w_ih_f2  = (const float*)d_in[9];
    const float* w_hh_f2  = (const float*)d_in[10];
    const float* b_f2     = (const float*)d_in[11];
    const float* w_ih_b2  = (const float*)d_in[12];
    const float* w_hh_b2  = (const float*)d_in[13];
    const float* b_b2     = (const float*)d_in[14];
    const float* cls_w    = (const float*)d_in[15];
    const float* cls_b    = (const float*)d_in[16];
    float* out = (float*)d_out;

    float *pE, *pPF, *pPB, *pO1, *pO2;
    cudaGetSymbolAddress((void**)&pE,  g_e);
    cudaGetSymbolAddress((void**)&pPF, g_preF);
    cudaGetSymbolAddress((void**)&pPB, g_preB);
    cudaGetSymbolAddress((void**)&pO1, g_out1);
    cudaGetSymbolAddress((void**)&pO2, g_out2);

    cudaFuncSetAttribute(lstm_layer_kernel,
                         cudaFuncAttributeMaxDynamicSharedMemorySize,
                         LSTM_SMEM_BYTES);

    const int M = B_ * T_;
    const dim3 pre_grid(H4_ / 64, M / 128);     // (32, 128)

    detect_kernel<<<1, 64>>>(x, lengths);
    gather_kernel<<<M, 64>>>(x, emb);
    init_state_kernel<<<256, 256>>>();

    mma_pre_gemm<<<pre_grid, 256>>>(pE, w_ih_f1, b_f1, pPF, E_);
    mma_pre_gemm<<<pre_grid, 256>>>(pE, w_ih_b1, b_b1, pPB, E_);
    lstm_layer_kernel<<<128, 512, LSTM_SMEM_BYTES>>>(pPF, pPB, w_hh_f1, w_hh_b1,
                                                     pO1);

    init_state_kernel<<<256, 256>>>();

    mma_pre_gemm<<<pre_grid, 256>>>(pO1, w_ih_f2, b_f2, pPF, 2 * H_);
    mma_pre_gemm<<<pre_grid, 256>>>(pO1, w_ih_b2, b_b2, pPB, 2 * H_);
    lstm_layer_kernel<<<128, 512, LSTM_SMEM_BYTES>>>(pPF, pPB, w_hh_f2, w_hh_b2,
                                                     pO2);

    classifier_kernel<<<M / 8, 256>>>(cls_w, cls_b, out);
}

// round 7
// speedup vs baseline: 3.7594x; 1.3616x over previous
#include <cuda_runtime.h>
#include <cstdint>
#include <cstdio>

#define B_    64
#define T_    256
#define E_    256
#define H_    512
#define H4_   2048
#define TAGS_ 50

#define GP_J  68                         // split-K partial col stride (conflict-free)
#define PRE_S 20                         // pre-GEMM smem row stride (floats)
// lstm smem: sW 512*32 + sH 512*64 + lens
#define LSTM_SMEM_FLOATS (512 * 32 + 512 * 64 + 64)
#define LSTM_SMEM_BYTES  (LSTM_SMEM_FLOATS * 4)

// ---------------- scratch ----------------------------------------------------
__device__ float g_e[B_ * T_ * E_];
__device__ float g_preF[(size_t)B_ * T_ * H4_];
__device__ float g_preB[(size_t)B_ * T_ * H4_];
__device__ float g_out1[(size_t)B_ * T_ * 2 * H_];
__device__ float g_out2[(size_t)B_ * T_ * 2 * H_];
__device__ float g_hF[2][H_ * B_];          // transposed: [k][row]
__device__ float g_hB[2][H_ * B_];
__device__ __align__(128) unsigned g_barF;  // fwd barrier counter
__device__ __align__(128) unsigned g_barB;  // bwd barrier counter
__device__ int g_is64;
__device__ int g_len[B_];

// ---------------- helpers ----------------------------------------------------
__device__ __forceinline__ float sig_fast(float x) {
    return __fdividef(1.0f, 1.0f + __expf(-x));
}
__device__ __forceinline__ float tanh_fast(float x) {
    const float e = __expf(-2.0f * x);
    return __fdividef(1.0f - e, 1.0f + e);
}
// D(16x8,f32) += A(16x8,tf32,row) * B(8x8,tf32,col); fp32 bits, HW truncates.
__device__ __forceinline__ void mma_tf32(float d[4], const unsigned a[4],
                                         const unsigned b[2]) {
    asm volatile(
        "mma.sync.aligned.m16n8k8.row.col.f32.tf32.tf32.f32 "
        "{%0,%1,%2,%3}, {%4,%5,%6,%7}, {%8,%9}, {%0,%1,%2,%3};"
        : "+f"(d[0]), "+f"(d[1]), "+f"(d[2]), "+f"(d[3])
        : "r"(a[0]), "r"(a[1]), "r"(a[2]), "r"(a[3]), "r"(b[0]), "r"(b[1]));
}
__device__ __forceinline__ void cp16(float* dst_smem, const float* src) {
    const unsigned d = (unsigned)__cvta_generic_to_shared(dst_smem);
    asm volatile("cp.async.cg.shared.global [%0], [%1], 16;"
                 :: "r"(d), "l"(src) : "memory");
}
#define CP_COMMIT() asm volatile("cp.async.commit_group;" ::: "memory")

// ---------------- dtype detect + lengths -------------------------------------
__global__ void detect_kernel(const void* x, const void* lengths) {
    __shared__ int s64;
    if (threadIdx.x == 0) {
        const int* xi = (const int*)x;
        int flag = 1;
        for (int i = 1; i <= 16; ++i)
            if (xi[2 * i + 1] != 0) flag = 0;
        g_is64 = flag;
        s64 = flag;
    }
    __syncthreads();
    if (threadIdx.x < B_) {
        int l = s64 ? (int)((const long long*)lengths)[threadIdx.x]
                    : ((const int*)lengths)[threadIdx.x];
        g_len[threadIdx.x] = l;
    }
}

// ---------------- embedding gather -------------------------------------------
__global__ void gather_kernel(const void* x, const float* __restrict__ emb) {
    const int row = blockIdx.x;
    long long idx = g_is64 ? ((const long long*)x)[row]
                           : (long long)((const int*)x)[row];
    const float4* src = (const float4*)(emb + (size_t)idx * E_);
    float4* dst = (float4*)(g_e + (size_t)row * E_);
    dst[threadIdx.x] = src[threadIdx.x];
}

// ---------------- init --------------------------------------------------------
__global__ void init_state_kernel() {
    int i = blockIdx.x * blockDim.x + threadIdx.x;
    const int n = 2 * B_ * H_;
    if (i < n) {
        ((float*)g_hF)[i] = 0.0f;
        ((float*)g_hB)[i] = 0.0f;
    }
    if (i == 0) { g_barF = 0u; g_barB = 0u; }
}

// ---------------- tf32 MMA pre-GEMM: C[M,2048] = A[M,K] @ W[2048,K]^T + bias --
// CTA 128x64, 8 warps (4m x 2n of 32x32), k-chunk 16, 3-stage cp.async pipeline,
// smem [row][k] stride 20 (conflict-free frags, 16B-contiguous copies), no cvt.
__global__ void __launch_bounds__(256, 2)
mma_pre_gemm(const float* __restrict__ A, const float* __restrict__ W,
             const float* __restrict__ bias, float* __restrict__ C, int K) {
    __shared__ __align__(16) float sA[3][128 * PRE_S];
    __shared__ __align__(16) float sB[3][64 * PRE_S];
    const int tid  = threadIdx.x;
    const int lane = tid & 31;
    const int wrp  = tid >> 5;
    const int tg   = lane >> 2;
    const int tk   = lane & 3;
    const int bm = blockIdx.y * 128;
    const int bn = blockIdx.x * 64;
    const int wm = (wrp >> 1) * 32;
    const int wn = (wrp & 1) * 32;

    // loader mapping (16B chunks)
    const int ar0 = tid >> 2;              // A chunk 0 row (0..63 via j loop offset)
    const int ak4 = (tid & 3) * 4;
    const int br  = tid >> 2;              // B row 0..63
    const int bk4 = (tid & 3) * 4;

    float d[2][4][4];
#pragma unroll
    for (int mi = 0; mi < 2; ++mi)
#pragma unroll
        for (int ni = 0; ni < 4; ++ni)
#pragma unroll
            for (int q = 0; q < 4; ++q) d[mi][ni][q] = 0.0f;

    const int NT = K >> 4;

    auto issue_stage = [&](int buf, int kt) {
#pragma unroll
        for (int j = 0; j < 2; ++j) {
            const int row = ar0 + j * 64;
            cp16(&sA[buf][row * PRE_S + ak4],
                 A + (size_t)(bm + row) * K + kt * 16 + ak4);
        }
        cp16(&sB[buf][br * PRE_S + bk4],
             W + (size_t)(bn + br) * K + kt * 16 + bk4);
        CP_COMMIT();
    };

    issue_stage(0, 0);
    issue_stage(1, 1);

    for (int i = 0; i < NT; ++i) {
        if (i + 1 < NT)
            asm volatile("cp.async.wait_group 1;" ::: "memory");
        else
            asm volatile("cp.async.wait_group 0;" ::: "memory");
        __syncthreads();
        const int buf = i % 3;
        const unsigned* uA = (const unsigned*)sA[buf];
        const unsigned* uB = (const unsigned*)sB[buf];
#pragma unroll
        for (int ks8 = 0; ks8 < 2; ++ks8) {
            const int kb = ks8 * 8;
            unsigned af[2][4], bf[4][2];
#pragma unroll
            for (int mi = 0; mi < 2; ++mi) {
                const int rb = wm + mi * 16;
                af[mi][0] = uA[(rb + tg) * PRE_S + kb + tk];
                af[mi][1] = uA[(rb + tg + 8) * PRE_S + kb + tk];
                af[mi][2] = uA[(rb + tg) * PRE_S + kb + tk + 4];
                af[mi][3] = uA[(rb + tg + 8) * PRE_S + kb + tk + 4];
            }
#pragma unroll
            for (int ni = 0; ni < 4; ++ni) {
                const int nb = wn + ni * 8;
                bf[ni][0] = uB[(nb + tg) * PRE_S + kb + tk];
                bf[ni][1] = uB[(nb + tg) * PRE_S + kb + tk + 4];
            }
#pragma unroll
            for (int mi = 0; mi < 2; ++mi)
#pragma unroll
                for (int ni = 0; ni < 4; ++ni)
                    mma_tf32(d[mi][ni], af[mi], bf[ni]);
        }
        if (i + 2 < NT) issue_stage((i + 2) % 3, i + 2);
    }

#pragma unroll
    for (int mi = 0; mi < 2; ++mi) {
        const int r0 = bm + wm + mi * 16 + tg;
#pragma unroll
        for (int ni = 0; ni < 4; ++ni) {
            const int col = bn + wn + ni * 8 + tk * 2;
            const float2 bb = *(const float2*)&bias[col];
            *(float2*)&C[(size_t)r0 * H4_ + col] =
                make_float2(d[mi][ni][0] + bb.x, d[mi][ni][1] + bb.y);
            *(float2*)&C[(size_t)(r0 + 8) * H4_ + col] =
                make_float2(d[mi][ni][2] + bb.x, d[mi][ni][3] + bb.y);
        }
    }
}

// ---------------- persistent BiLSTM layer (tf32 MMA recurrence) ---------------
// 128 CTAs x 512 threads. bx>>6 = dir, bx&63 = column group (8 h-cols, 32 gate
// cols). W_hh slice resident in smem (raw fp32, swizzled). Per step: each
// warp-pair cp.async-stages ONLY its own 16KB k-slice, syncs via a 64-thread
// named barrier, and starts MMA immediately (dataflow staging). Split-K
// partials -> smem, reduce + fast-activation EW, per-direction grid barrier.
__global__ void __launch_bounds__(512, 1)
lstm_layer_kernel(const float* __restrict__ preF, const float* __restrict__ preB,
                  const float* __restrict__ whF, const float* __restrict__ whB,
                  float* __restrict__ outBuf) {
    extern __shared__ __align__(16) float smem_[];
    float* sW = smem_;                          // [512][32] swizzled
    float* sH = smem_ + 512 * 32;               // [512][64]; reused as sGp[8][32][68]
    int* sLen = (int*)(smem_ + 512 * 32 + 512 * 64);
    unsigned* uW = (unsigned*)sW;
    unsigned* uH = (unsigned*)sH;

    const int tid  = threadIdx.x;
    const int bx   = blockIdx.x;
    const int dir  = bx >> 6;
    const int cg   = bx & 63;
    const int lane = tid & 31;
    const int wrp  = tid >> 5;
    const int tg   = lane >> 2;
    const int tk   = lane & 3;
    const int ks   = wrp >> 1;                  // K slice 0..7 (64 k each)
    const int ns   = wrp & 1;                   // N half (16 gate cols)

    const float* __restrict__ pre = dir ? preB : preF;
    const float* __restrict__ W   = dir ? whB : whF;
    float* hbase = dir ? &g_hB[0][0] : &g_hF[0][0];
    unsigned* barp = dir ? &g_barB : &g_barF;

    if (tid < B_) sLen[tid] = g_len[tid];
    // W_hh slice -> smem [k][n] swizzled, raw fp32 (coalesced in k)
    for (int idx = tid; idx < 32 * 512; idx += 512) {
        const int j = idx >> 9;                 // gate col 0..31
        const int k = idx & 511;
        const int gcol = (j >> 3) * 512 + cg * 8 + (j & 7);
        sW[k * 32 + (j ^ ((k & 3) << 3))] = W[(size_t)gcol * H_ + k];
    }
    __syncthreads();

    // elementwise mapping: 1 elem/thread
    const int row = tid >> 3;                   // 0..63
    const int hj  = tid & 7;
    const int len = sLen[row];

    float creg = 0.f, hreg = 0.f;

    // prefetch pre for t=0 (always valid: len >= 1)
    float p[4];
    {
        const int pos = dir ? (len - 1) : 0;
        const size_t pb = ((size_t)row * T_ + pos) * H4_ + cg * 8 + hj;
#pragma unroll
        for (int g = 0; g < 4; ++g) p[g] = __ldg(&pre[pb + g * 512]);
    }

    for (int t = 0; t < T_; ++t) {
        // ---- stage OWN k-slice via cp.async; pair-sync via named barrier ----
        {
            const float* hsrc = hbase + (size_t)(t & 1) * (H_ * B_);
            const int cbase = ks * 1024 + (wrp & 1) * 512;   // 16B-chunk index base
#pragma unroll
            for (int i = 0; i < 16; ++i) {
                const int idx = cbase + i * 32 + lane;
                const int k  = idx >> 4;
                const int mq = (idx & 15) << 2;
                cp16(&sH[k * 64 + (mq ^ ((k & 3) << 3))], hsrc + idx * 4);
            }
            CP_COMMIT();
            asm volatile("cp.async.wait_group 0;" ::: "memory");
            asm volatile("bar.sync %0, 64;" :: "r"(1 + ks) : "memory");
        }

        // ---- MMA: warp (ks, ns): m64 n16 k64 ----
        float d[4][2][4];
#pragma unroll
        for (int mi = 0; mi < 4; ++mi)
#pragma unroll
            for (int ni = 0; ni < 2; ++ni)
#pragma unroll
                for (int q = 0; q < 4; ++q) d[mi][ni][q] = 0.0f;

#pragma unroll
        for (int kc = 0; kc < 8; ++kc) {
            const int kb = ks * 64 + kc * 8;
            const int sw = tk << 3;
            unsigned af[4][4], bf[2][2];
#pragma unroll
            for (int mi = 0; mi < 4; ++mi) {
                const int rb = mi * 16;
                af[mi][0] = uH[(kb + tk) * 64 + ((rb + tg) ^ sw)];
                af[mi][1] = uH[(kb + tk) * 64 + ((rb + tg + 8) ^ sw)];
                af[mi][2] = uH[(kb + tk + 4) * 64 + ((rb + tg) ^ sw)];
                af[mi][3] = uH[(kb + tk + 4) * 64 + ((rb + tg + 8) ^ sw)];
            }
#pragma unroll
            for (int ni = 0; ni < 2; ++ni) {
                const int nb = ns * 16 + ni * 8;
                bf[ni][0] = uW[(kb + tk) * 32 + ((nb + tg) ^ sw)];
                bf[ni][1] = uW[(kb + tk + 4) * 32 + ((nb + tg) ^ sw)];
            }
#pragma unroll
            for (int mi = 0; mi < 4; ++mi)
#pragma unroll
                for (int ni = 0; ni < 2; ++ni)
                    mma_tf32(d[mi][ni], af[mi], bf[ni]);
        }
        __syncthreads();   // all warps done reading sH (sGp aliases it)

        // ---- dump split-K partials: sGp[ks][col][row] (conflict-free) ----
        float* sGp = sH;   // [8][32][GP_J]
        {
            float* g = sGp + ks * (32 * GP_J);
#pragma unroll
            for (int mi = 0; mi < 4; ++mi) {
                const int mb = mi * 16 + tg;
#pragma unroll
                for (int ni = 0; ni < 2; ++ni) {
                    const int nb = ns * 16 + ni * 8 + tk * 2;
                    g[nb * GP_J + mb]           = d[mi][ni][0];
                    g[(nb + 1) * GP_J + mb]     = d[mi][ni][1];
                    g[nb * GP_J + mb + 8]       = d[mi][ni][2];
                    g[(nb + 1) * GP_J + mb + 8] = d[mi][ni][3];
                }
            }
        }
        __syncthreads();

        // ---- reduce + elementwise (1 elem/thread) ----
        float* hnext = hbase + (size_t)((t + 1) & 1) * (H_ * B_);
        {
            const bool valid = (t < len);
            const int pos = dir ? (valid ? (len - 1 - t) : t) : t;

            float gi = 0.f, gf = 0.f, gg = 0.f, go = 0.f;
#pragma unroll
            for (int w = 0; w < 8; ++w) {
                const float* gp = sGp + w * (32 * GP_J) + row;
                gi += gp[(hj)      * GP_J];
                gf += gp[(8 + hj)  * GP_J];
                gg += gp[(16 + hj) * GP_J];
                go += gp[(24 + hj) * GP_J];
            }
            gi += p[0]; gf += p[1]; gg += p[2]; go += p[3];

            const float iv = sig_fast(gi);
            const float fv = sig_fast(gf);
            const float gv = tanh_fast(gg);
            const float ov = sig_fast(go);
            const float cn = fv * creg + iv * gv;
            const float hn = ov * tanh_fast(cn);
            if (valid) { creg = cn; hreg = hn; }

            __stcg(&hnext[(cg * 8 + hj) * 64 + row], hreg);   // critical path first
            outBuf[((size_t)row * T_ + pos) * (2 * H_) + dir * H_ + cg * 8 + hj] =
                valid ? hn : 0.0f;
        }

        // ---- prefetch pre for t+1 ----
        if (t + 1 < T_) {
            const int tn = t + 1;
            const bool v = (tn < len);
            const int pos = dir ? (v ? (len - 1 - tn) : tn) : tn;
            const size_t pb = ((size_t)row * T_ + pos) * H4_ + cg * 8 + hj;
#pragma unroll
            for (int g = 0; g < 4; ++g) p[g] = __ldg(&pre[pb + g * 512]);
        }

        // ---- per-direction grid barrier (64 arrivals) ----
        __syncthreads();
        if (tid == 0) {
            __threadfence();
            atomicAdd(barp, 1u);
            const unsigned tgt = (unsigned)(t + 1) * 64u;
            unsigned v;
            do {
                asm volatile("ld.relaxed.gpu.global.u32 %0, [%1];"
                             : "=r"(v) : "l"(barp));
            } while (v < tgt);
            asm volatile("fence.acq_rel.gpu;" ::: "memory");
        }
        __syncthreads();
    }
}

// ---------------- classifier --------------------------------------------------
__global__ void __launch_bounds__(256, 1)
classifier_kernel(const float* __restrict__ clsW, const float* __restrict__ clsB,
                  float* __restrict__ out) {
    __shared__ __align__(16) float sX[8][1028];
    const int tid = threadIdx.x;
    const size_t r0 = (size_t)blockIdx.x * 8;
    const float* src = g_out2 + r0 * (2 * H_);
    for (int i = tid; i < 8 * 256; i += 256) {
        const int rr = i >> 8;
        const int kk = (i & 255) * 4;
        *(float4*)&sX[rr][kk] = *(const float4*)(src + (size_t)rr * 1024 + kk);
    }
    __syncthreads();
    for (int e = tid; e < 8 * TAGS_; e += 256) {
        const int r = e & 7;
        const int c = e >> 3;
        const float* w = clsW + (size_t)c * 1024;
        float s0 = 0.f, s1 = 0.f, s2 = 0.f, s3 = 0.f;
#pragma unroll 8
        for (int k = 0; k < 1024; k += 4) {
            const float4 a = *(const float4*)&sX[r][k];
            const float4 b = __ldg((const float4*)(w + k));
            s0 += a.x * b.x; s1 += a.y * b.y; s2 += a.z * b.z; s3 += a.w * b.w;
        }
        out[(r0 + r) * TAGS_ + c] = s0 + s1 + s2 + s3 + clsB[c];
    }
}

// ---------------- host launcher -----------------------------------------------
extern "C" void kernel_launch(void* const* d_in, const int* in_sizes, int n_in,
                              void* d_out, int out_size) {
    (void)in_sizes; (void)n_in; (void)out_size;
    const void*  x        = d_in[0];
    const void*  lengths  = d_in[1];
    const float* emb      = (const float*)d_in[2];
    const float* w_ih_f1  = (const float*)d_in[3];
    const float* w_hh_f1  = (const float*)d_in[4];
    const float* b_f1     = (const float*)d_in[5];
    const float* w_ih_b1  = (const float*)d_in[6];
    const float* w_hh_b1  = (const float*)d_in[7];
    const float* b_b1     = (const float*)d_in[8];
    const float* w_ih_f2  = (const float*)d_in[9];
    const float* w_hh_f2  = (const float*)d_in[10];
    const float* b_f2     = (const float*)d_in[11];
    const float* w_ih_b2  = (const float*)d_in[12];
    const float* w_hh_b2  = (const float*)d_in[13];
    const float* b_b2     = (const float*)d_in[14];
    const float* cls_w    = (const float*)d_in[15];
    const float* cls_b    = (const float*)d_in[16];
    float* out = (float*)d_out;

    float *pE, *pPF, *pPB, *pO1, *pO2;
    cudaGetSymbolAddress((void**)&pE,  g_e);
    cudaGetSymbolAddress((void**)&pPF, g_preF);
    cudaGetSymbolAddress((void**)&pPB, g_preB);
    cudaGetSymbolAddress((void**)&pO1, g_out1);
    cudaGetSymbolAddress((void**)&pO2, g_out2);

    cudaFuncSetAttribute(lstm_layer_kernel,
                         cudaFuncAttributeMaxDynamicSharedMemorySize,
                         LSTM_SMEM_BYTES);

    const int M = B_ * T_;
    const dim3 pre_grid(H4_ / 64, M / 128);     // (32, 128)

    detect_kernel<<<1, 64>>>(x, lengths);
    gather_kernel<<<M, 64>>>(x, emb);
    init_state_kernel<<<256, 256>>>();

    mma_pre_gemm<<<pre_grid, 256>>>(pE, w_ih_f1, b_f1, pPF, E_);
    mma_pre_gemm<<<pre_grid, 256>>>(pE, w_ih_b1, b_b1, pPB, E_);
    lstm_layer_kernel<<<128, 512, LSTM_SMEM_BYTES>>>(pPF, pPB, w_hh_f1, w_hh_b1,
                                                     pO1);

    init_state_kernel<<<256, 256>>>();

    mma_pre_gemm<<<pre_grid, 256>>>(pO1, w_ih_f2, b_f2, pPF, 2 * H_);
    mma_pre_gemm<<<pre_grid, 256>>>(pO1, w_ih_b2, b_b2, pPB, 2 * H_);
    lstm_layer_kernel<<<128, 512, LSTM_SMEM_BYTES>>>(pPF, pPB, w_hh_f2, w_hh_b2,
                                                     pO2);

    classifier_kernel<<<M / 8, 256>>>(cls_w, cls_b, out);
}